// round 7
// baseline (speedup 1.0000x reference)
#include <cuda_runtime.h>
#include <cuda_bf16.h>
#include <cstdint>

#define B_  4096
#define T_  256
#define D_  20
#define E_  64
#define H_  16
#define G4_ 64
#define TGRP 32
#define SGROW 80

// G layout: [b][t(256)][c(64)]
__device__ float g_G[(size_t)B_ * G4_ * T_];
__device__ float g_hf[B_ * H_];

typedef unsigned long long u64;

__device__ __forceinline__ float ex2a(float x){ float y; asm("ex2.approx.f32 %0,%1;":"=f"(y):"f"(x)); return y; }
__device__ __forceinline__ float rcpa(float x){ float y; asm("rcp.approx.f32 %0,%1;":"=f"(y):"f"(x)); return y; }
__device__ __forceinline__ u64 pack2(float a,float b){ u64 r; asm("mov.b64 %0,{%1,%2};":"=l"(r):"f"(a),"f"(b)); return r; }
__device__ __forceinline__ void unpack2(u64 v,float&a,float&b){ asm("mov.b64 {%0,%1},%2;":"=f"(a),"=f"(b):"l"(v)); }
__device__ __forceinline__ u64 fma2(u64 a,u64 b,u64 c){ u64 d; asm("fma.rn.f32x2 %0,%1,%2,%3;":"=l"(d):"l"(a),"l"(b),"l"(c)); return d; }
__device__ __forceinline__ u64 add2(u64 a,u64 b){ u64 d; asm("add.rn.f32x2 %0,%1,%2;":"=l"(d):"l"(a),"l"(b)); return d; }
__device__ __forceinline__ uint32_t smem_u32(const void* p){
    uint32_t a; asm("{ .reg .u64 t; cvta.to.shared.u64 t, %1; cvt.u32.u64 %0, t; }":"=r"(a):"l"(p)); return a;
}
__device__ __forceinline__ void mma16816(float& c0, float& c1, float& c2, float& c3,
                                         uint32_t a0, uint32_t a1, uint32_t a2, uint32_t a3,
                                         uint32_t b0, uint32_t b1){
    asm volatile("mma.sync.aligned.m16n8k16.row.col.f32.bf16.bf16.f32 "
        "{%0,%1,%2,%3}, {%4,%5,%6,%7}, {%8,%9}, {%0,%1,%2,%3};"
        : "+f"(c0),"+f"(c1),"+f"(c2),"+f"(c3)
        : "r"(a0),"r"(a1),"r"(a2),"r"(a3),"r"(b0),"r"(b1));
}
__device__ __forceinline__ void ldm4(uint32_t& r0, uint32_t& r1, uint32_t& r2, uint32_t& r3, uint32_t a){
    asm volatile("ldmatrix.sync.aligned.m8n8.x4.shared.b16 {%0,%1,%2,%3}, [%4];"
        : "=r"(r0),"=r"(r1),"=r"(r2),"=r"(r3) : "r"(a));
}
__device__ __forceinline__ void split2(u64 p, uint32_t& hi, uint32_t& lo){
    float v0, v1; unpack2(p, v0, v1);
    v0 = fmaxf(v0, 0.f); v1 = fmaxf(v1, 0.f);
    __nv_bfloat16 h0 = __float2bfloat16(v0), h1 = __float2bfloat16(v1);
    __nv_bfloat16 l0 = __float2bfloat16(v0 - __bfloat162float(h0));
    __nv_bfloat16 l1 = __float2bfloat16(v1 - __bfloat162float(h1));
    hi = (uint32_t)__bfloat16_as_ushort(h0) | ((uint32_t)__bfloat16_as_ushort(h1) << 16);
    lo = (uint32_t)__bfloat16_as_ushort(l0) | ((uint32_t)__bfloat16_as_ushort(l1) << 16);
}

// SMEM byte offsets (phase1, 128-row CTA)
#define OAH 0u              // 128 x 144B hi
#define OAL 18432u          // 128 x 144B lo
#define OWH 36864u          // 64 x 144B hi
#define OWL 46080u
#define OXS 55296u          // 128 x 21 f32
#define OW0 66048u          // 20 x 64 f32
#define OB0 71168u
#define OBF 71424u
#define SMEM1 71680u

// ---------------- Phase 1: 128 rows/CTA, 3 CTAs/SM, 32x32 warp tiles ----------------
__global__ void __launch_bounds__(256, 3) k_phase1(
    const float* __restrict__ x, const float* __restrict__ W0,
    const float* __restrict__ b0, const float* __restrict__ Wf,
    const float* __restrict__ bf)
{
    extern __shared__ char sm[];
    const uint32_t sb = smem_u32(sm);
    float* xs  = (float*)(sm + OXS);
    float* W0s = (float*)(sm + OW0);
    float* b0s = (float*)(sm + OB0);
    float* bfs = (float*)(sm + OBF);

    const int tid = threadIdx.x, wid = tid >> 5, lane = tid & 31;
    const int b  = blockIdx.x >> 1;
    const int bh = blockIdx.x & 1;

    // coalesced staging
    const float* xb = x + ((size_t)b * T_ + bh * 128) * D_;
    for (int i = tid; i < 128 * D_; i += 256) { int r = i / D_, d = i - r * D_; xs[r * 21 + d] = xb[i]; }
    for (int i = tid; i < D_ * E_; i += 256) W0s[i] = W0[i];
    if (tid < 64) { b0s[tid] = b0[tid]; bfs[tid] = bf[tid]; }
    for (int i = tid; i < 4096; i += 256) {
        int k = i >> 6, c = i & 63;
        float v = Wf[i];
        __nv_bfloat16 h = __float2bfloat16(v);
        __nv_bfloat16 l = __float2bfloat16(v - __bfloat162float(h));
        *(unsigned short*)(sm + OWH + c * 144 + k * 2) = __bfloat16_as_ushort(h);
        *(unsigned short*)(sm + OWL + c * 144 + k * 2) = __bfloat16_as_ushort(l);
    }
    __syncthreads();

    // ---- Step A: 2 threads per row, 32 cols each ----
    {
        const int r = tid >> 1, hf = tid & 1;
        const int c0 = hf * 32;
        u64 acc2[16];
        #pragma unroll
        for (int q = 0; q < 16; q++) acc2[q] = pack2(b0s[c0 + 2*q], b0s[c0 + 2*q + 1]);
        #pragma unroll 4
        for (int d = 0; d < D_; d++) {
            float xv = xs[r * 21 + d];
            u64 xp = pack2(xv, xv);
            const ulonglong2* wr = (const ulonglong2*)&W0s[d * 64 + c0];
            #pragma unroll
            for (int q = 0; q < 8; q++) {
                ulonglong2 ww = wr[q];
                acc2[2*q]   = fma2(xp, ww.x, acc2[2*q]);
                acc2[2*q+1] = fma2(xp, ww.y, acc2[2*q+1]);
            }
        }
        #pragma unroll
        for (int q4 = 0; q4 < 4; q4++) {
            uint4 hv, lv;
            split2(acc2[4*q4+0], hv.x, lv.x);
            split2(acc2[4*q4+1], hv.y, lv.y);
            split2(acc2[4*q4+2], hv.z, lv.z);
            split2(acc2[4*q4+3], hv.w, lv.w);
            *(uint4*)(sm + OAH + r * 144 + c0 * 2 + q4 * 16) = hv;
            *(uint4*)(sm + OAL + r * 144 + c0 * 2 + q4 * 16) = lv;
        }
    }
    __syncthreads();

    // ---- Step B: warp = 32t x 32c ----
    const int t0    = (wid >> 1) * 32;
    const int cbase = (wid & 1) * 32;
    const int cb = (lane & 3) * 2;

    float acc[2][4][4];
    #pragma unroll
    for (int nt = 0; nt < 4; nt++) {
        float2 bv = *(float2*)&bfs[cbase + nt * 8 + cb];
        #pragma unroll
        for (int m = 0; m < 2; m++) {
            acc[m][nt][0] = bv.x; acc[m][nt][1] = bv.y;
            acc[m][nt][2] = bv.x; acc[m][nt][3] = bv.y;
        }
    }

    const int arow = ((lane >> 3) & 1) * 8 + (lane & 7);
    const int acol = (lane >> 4) * 16;

    #pragma unroll
    for (int ks = 0; ks < 4; ks++) {
        const int k0 = ks * 16;
        uint32_t Ah[2][4], Al[2][4];
        #pragma unroll
        for (int mt = 0; mt < 2; mt++) {
            uint32_t ad = sb + OAH + (uint32_t)(t0 + mt * 16 + arow) * 144 + (uint32_t)(k0 * 2 + acol);
            ldm4(Ah[mt][0], Ah[mt][1], Ah[mt][2], Ah[mt][3], ad);
            ldm4(Al[mt][0], Al[mt][1], Al[mt][2], Al[mt][3], ad + (OAL - OAH));
        }
        #pragma unroll
        for (int nt = 0; nt < 4; nt++) {
            const uint32_t boff = (uint32_t)((cbase + nt * 8 + (lane >> 2)) * 144 + k0 * 2 + (lane & 3) * 4);
            uint32_t bh0 = *(const uint32_t*)(sm + OWH + boff);
            uint32_t bh1 = *(const uint32_t*)(sm + OWH + boff + 16);
            uint32_t bl0 = *(const uint32_t*)(sm + OWL + boff);
            uint32_t bl1 = *(const uint32_t*)(sm + OWL + boff + 16);
            #pragma unroll
            for (int mt = 0; mt < 2; mt++) {
                mma16816(acc[mt][nt][0], acc[mt][nt][1], acc[mt][nt][2], acc[mt][nt][3],
                         Ah[mt][0], Ah[mt][1], Ah[mt][2], Ah[mt][3], bh0, bh1);
                mma16816(acc[mt][nt][0], acc[mt][nt][1], acc[mt][nt][2], acc[mt][nt][3],
                         Ah[mt][0], Ah[mt][1], Ah[mt][2], Ah[mt][3], bl0, bl1);
                mma16816(acc[mt][nt][0], acc[mt][nt][1], acc[mt][nt][2], acc[mt][nt][3],
                         Al[mt][0], Al[mt][1], Al[mt][2], Al[mt][3], bh0, bh1);
            }
        }
    }

    // ---- Direct fragment stores ----
    {
        float* Gb = g_G + (size_t)b * (G4_ * T_) + (size_t)(bh * 128) * 64;
        #pragma unroll
        for (int mt = 0; mt < 2; mt++) {
            const int t = t0 + mt * 16 + (lane >> 2);
            #pragma unroll
            for (int nt = 0; nt < 4; nt++) {
                const int c = cbase + nt * 8 + cb;
                *(float2*)&Gb[(size_t)t * 64 + c]       = make_float2(acc[mt][nt][0], acc[mt][nt][1]);
                *(float2*)&Gb[(size_t)(t + 8) * 64 + c] = make_float2(acc[mt][nt][2], acc[mt][nt][3]);
            }
        }
    }
}

// ---------------- Phase 2: forward scan (unchanged from R6) ----------------
__global__ void __launch_bounds__(128) k_scan(const float* __restrict__ Wf)
{
    __shared__ float sg[4][2][8 * SGROW];

    const int tid = threadIdx.x, w = tid >> 5, l = tid & 31;
    const int b = blockIdx.x * 4 + w;
    const int j = l & 15;
    const int cA = (l < 16) ? l : (32 + j);
    const int cB = cA + 16;
    const int offA = cA + ((cA >> 5) << 4);
    const int offB = cB + ((cB >> 5) << 4);

    u64 wp[16];
    #pragma unroll
    for (int k = 0; k < 16; k++)
        wp[k] = pack2(Wf[(E_ + k) * G4_ + cA], Wf[(E_ + k) * G4_ + cB]);

    const float* Gb = g_G + (size_t)b * (G4_ * T_);

    int soff[4];
    #pragma unroll
    for (int k = 0; k < 4; k++) {
        int f  = l + 32 * k;
        int ti = f >> 4;
        int c4 = f & 15;
        soff[k] = ti * SGROW + c4 * 4 + ((c4 >> 3) << 4);
    }

    float h = 0.f, c = 0.f;

    const float L2E = 1.4426950408889634f;
    float kU, bU, kV, aV, bV;
    if (l < 16) { kU = -L2E; bU = 0.f;   kV = -2.f * L2E; aV = 2.f; bV = -1.f; }
    else        { kU = -L2E; bU = -L2E;  kV = -L2E;       aV = 1.f; bV =  0.f; }

    float4 r[4];
    {
        const float4* src = (const float4*)Gb;
        #pragma unroll
        for (int k = 0; k < 4; k++) r[k] = src[l + 32 * k];
        #pragma unroll
        for (int k = 0; k < 4; k++) *(float4*)&sg[w][0][soff[k]] = r[k];
    }
    __syncwarp();

    for (int tg = 0; tg < TGRP; ++tg) {
        const int buf = tg & 1;
        if (tg < TGRP - 1) {
            const float4* src = (const float4*)(Gb + (size_t)(tg + 1) * 512);
            #pragma unroll
            for (int k = 0; k < 4; k++) r[k] = src[l + 32 * k];
        }
        const float* sgb = &sg[w][buf][0];
        #pragma unroll
        for (int i = 0; i < 8; i++) {
            float ga = sgb[i * SGROW + offA];
            float gb = sgb[i * SGROW + offB];
            float h0  = __shfl_sync(0xffffffffu, h, 0);
            float h1  = __shfl_sync(0xffffffffu, h, 1);
            float h2  = __shfl_sync(0xffffffffu, h, 2);
            float h3  = __shfl_sync(0xffffffffu, h, 3);
            float h4  = __shfl_sync(0xffffffffu, h, 4);
            float h5  = __shfl_sync(0xffffffffu, h, 5);
            float h6  = __shfl_sync(0xffffffffu, h, 6);
            float h7  = __shfl_sync(0xffffffffu, h, 7);
            float h8  = __shfl_sync(0xffffffffu, h, 8);
            float h9  = __shfl_sync(0xffffffffu, h, 9);
            float h10 = __shfl_sync(0xffffffffu, h, 10);
            float h11 = __shfl_sync(0xffffffffu, h, 11);
            float h12 = __shfl_sync(0xffffffffu, h, 12);
            float h13 = __shfl_sync(0xffffffffu, h, 13);
            float h14 = __shfl_sync(0xffffffffu, h, 14);
            float h15 = __shfl_sync(0xffffffffu, h, 15);

            u64 a0p = pack2(ga, gb);
            a0p = fma2(pack2(h0, h0),   wp[0],  a0p);
            a0p = fma2(pack2(h1, h1),   wp[1],  a0p);
            a0p = fma2(pack2(h2, h2),   wp[2],  a0p);
            a0p = fma2(pack2(h3, h3),   wp[3],  a0p);
            u64 a1p = fma2(pack2(h4, h4),   wp[4],  0ULL);
            a1p = fma2(pack2(h5, h5),   wp[5],  a1p);
            a1p = fma2(pack2(h6, h6),   wp[6],  a1p);
            a1p = fma2(pack2(h7, h7),   wp[7],  a1p);
            u64 a2p = fma2(pack2(h8, h8),   wp[8],  0ULL);
            a2p = fma2(pack2(h9, h9),   wp[9],  a2p);
            a2p = fma2(pack2(h10, h10), wp[10], a2p);
            a2p = fma2(pack2(h11, h11), wp[11], a2p);
            u64 a3p = fma2(pack2(h12, h12), wp[12], 0ULL);
            a3p = fma2(pack2(h13, h13), wp[13], a3p);
            a3p = fma2(pack2(h14, h14), wp[14], a3p);
            a3p = fma2(pack2(h15, h15), wp[15], a3p);
            u64 acc = add2(add2(a0p, a1p), add2(a2p, a3p));
            float xA, xB; unpack2(acc, xA, xB);

            float u = rcpa(1.f + ex2a(fmaf(kU, xA, bU)));
            float v = fmaf(aV, rcpa(1.f + ex2a(kV * xB)), bV);
            float sf = __shfl_down_sync(0xffffffffu, u, 16);
            float so = __shfl_down_sync(0xffffffffu, v, 16);
            if (l < 16) {
                c = fmaf(sf, c, u * v);
                float th = fmaf(2.f, rcpa(1.f + ex2a(-2.f * L2E * c)), -1.f);
                h = so * th;
            }
        }
        if (tg < TGRP - 1) {
            #pragma unroll
            for (int k = 0; k < 4; k++) *(float4*)&sg[w][buf ^ 1][soff[k]] = r[k];
            __syncwarp();
        }
    }
    if (l < 16) g_hf[b * H_ + l] = h;
}

// ---------------- Tail: bwd single step + head MLP (unchanged) ----------------
__global__ void __launch_bounds__(256) k_tail(
    const float* __restrict__ x, const float* __restrict__ W0,
    const float* __restrict__ b0, const float* __restrict__ Wb,
    const float* __restrict__ bb,
    const float* __restrict__ W1, const float* __restrict__ b1,
    const float* __restrict__ W2, const float* __restrict__ b2,
    const float* __restrict__ W3, const float* __restrict__ b3,
    float* __restrict__ out)
{
    __shared__ float W0s[D_ * E_];
    __shared__ float Wbs[E_ * G4_];
    __shared__ float b0s[64], bbs[64];
    __shared__ float W1s[32 * 64], W2s[64 * 16], W3s[32];
    __shared__ float b1s[64], b2s[16], b3s[2];
    __shared__ float xsh[8][20];
    __shared__ __align__(16) float2 hes[8][64];
    __shared__ float hbs[8][16];
    __shared__ float insh[8][32], ush[8][64], vsh[8][16];

    const int tid = threadIdx.x, w = tid >> 5, l = tid & 31;
    const int b = blockIdx.x * 8 + w;

    for (int i = tid; i < D_ * E_;  i += 256) W0s[i] = W0[i];
    for (int i = tid; i < E_ * G4_; i += 256) Wbs[i] = Wb[i];
    for (int i = tid; i < 32 * 64;  i += 256) W1s[i] = W1[i];
    for (int i = tid; i < 64 * 16;  i += 256) W2s[i] = W2[i];
    if (tid < 32) W3s[tid] = W3[tid];
    if (tid < 64) { b0s[tid] = b0[tid]; bbs[tid] = bb[tid]; b1s[tid] = b1[tid]; }
    if (tid < 16) b2s[tid] = b2[tid];
    if (tid < 2)  b3s[tid] = b3[tid];
    __syncthreads();

    if (l < 20) xsh[w][l] = x[((size_t)b * T_ + (T_ - 1)) * D_ + l];
    __syncwarp();

    float a0 = b0s[l], a1 = b0s[l + 32];
    #pragma unroll
    for (int d = 0; d < D_; d++) {
        float xv = xsh[w][d];
        a0 = fmaf(xv, W0s[d * E_ + l],      a0);
        a1 = fmaf(xv, W0s[d * E_ + l + 32], a1);
    }
    a0 = fmaxf(a0, 0.f); a1 = fmaxf(a1, 0.f);
    hes[w][l]      = make_float2(a0, a0);
    hes[w][l + 32] = make_float2(a1, a1);
    __syncwarp();

    const int j = l & 15;
    const int cA = (l < 16) ? l : (32 + j);
    const int cB = cA + 16;
    u64 acc = pack2(bbs[cA], bbs[cB]);
    #pragma unroll 8
    for (int k = 0; k < E_; k++) {
        u64 hd = *(const u64*)&hes[w][k];
        acc = fma2(hd, pack2(Wbs[k * G4_ + cA], Wbs[k * G4_ + cB]), acc);
    }
    float xA, xB; unpack2(acc, xA, xB);

    const float L2E = 1.4426950408889634f;
    float kU, bU, kV, aV, bV;
    if (l < 16) { kU = -L2E; bU = 0.f;  kV = -2.f * L2E; aV = 2.f; bV = -1.f; }
    else        { kU = -L2E; bU = -L2E; kV = -L2E;       aV = 1.f; bV =  0.f; }
    float u = rcpa(1.f + ex2a(fmaf(kU, xA, bU)));
    float v = fmaf(aV, rcpa(1.f + ex2a(kV * xB)), bV);
    float so = __shfl_down_sync(0xffffffffu, v, 16);
    if (l < 16) {
        float cc = u * v;
        float th = fmaf(2.f, rcpa(1.f + ex2a(-2.f * L2E * cc)), -1.f);
        hbs[w][l] = so * th;
    }
    __syncwarp();

    insh[w][l] = (l < 16) ? g_hf[b * H_ + l] : hbs[w][l - 16];
    __syncwarp();

    float u0 = b1s[l], u1 = b1s[l + 32];
    #pragma unroll 8
    for (int k = 0; k < 32; k++) {
        float t = insh[w][k];
        u0 = fmaf(t, W1s[k * 64 + l],      u0);
        u1 = fmaf(t, W1s[k * 64 + l + 32], u1);
    }
    ush[w][l]      = fmaxf(u0, 0.f);
    ush[w][l + 32] = fmaxf(u1, 0.f);
    __syncwarp();

    if (l < 16) {
        float a = b2s[l];
        #pragma unroll 8
        for (int k = 0; k < 64; k++) a = fmaf(ush[w][k], W2s[k * 16 + l], a);
        vsh[w][l] = fmaxf(a, 0.f);
    }
    __syncwarp();

    if (l < 2) {
        float a = b3s[l];
        #pragma unroll
        for (int k = 0; k < 16; k++) a = fmaf(vsh[w][k], W3s[k * 2 + l], a);
        out[b * 2 + l] = a;
    }
}

extern "C" void kernel_launch(void* const* d_in, const int* in_sizes, int n_in,
                              void* d_out, int out_size)
{
    (void)in_sizes; (void)n_in; (void)out_size;
    const float* x  = (const float*)d_in[0];
    const float* W0 = (const float*)d_in[1];
    const float* b0 = (const float*)d_in[2];
    const float* Wf = (const float*)d_in[3];
    const float* bf = (const float*)d_in[4];
    const float* Wb = (const float*)d_in[5];
    const float* bb = (const float*)d_in[6];
    const float* W1 = (const float*)d_in[7];
    const float* b1 = (const float*)d_in[8];
    const float* W2 = (const float*)d_in[9];
    const float* b2 = (const float*)d_in[10];
    const float* W3 = (const float*)d_in[11];
    const float* b3 = (const float*)d_in[12];
    float* out = (float*)d_out;

    cudaFuncSetAttribute(k_phase1, cudaFuncAttributeMaxDynamicSharedMemorySize, (int)SMEM1);

    k_phase1<<<B_ * 2, 256, SMEM1>>>(x, W0, b0, Wf, bf);
    k_scan  <<<B_ / 4, 128>>>(Wf);
    k_tail  <<<B_ / 8, 256>>>(x, W0, b0, Wb, bb, W1, b1, W2, b2, W3, b3, out);
}

// round 8
// speedup vs baseline: 1.1338x; 1.1338x over previous
#include <cuda_runtime.h>
#include <cuda_bf16.h>
#include <cstdint>

#define B_  4096
#define T_  256
#define D_  20
#define E_  64
#define H_  16
#define G4_ 64
#define TGRP 32
#define SGROW 80

// G layout: [b][t(256)][c(64)]
__device__ float g_G[(size_t)B_ * G4_ * T_];
__device__ float g_hf[B_ * H_];
__device__ uint32_t g_WpkH[2048];   // prepacked Wf^T hi (bf16x2), [c][w(32)]
__device__ uint32_t g_WpkL[2048];   // prepacked Wf^T lo

typedef unsigned long long u64;

__device__ __forceinline__ float tanha(float x){ float y; asm("tanh.approx.f32 %0,%1;":"=f"(y):"f"(x)); return y; }
__device__ __forceinline__ u64 pack2(float a,float b){ u64 r; asm("mov.b64 %0,{%1,%2};":"=l"(r):"f"(a),"f"(b)); return r; }
__device__ __forceinline__ void unpack2(u64 v,float&a,float&b){ asm("mov.b64 {%0,%1},%2;":"=f"(a),"=f"(b):"l"(v)); }
__device__ __forceinline__ u64 fma2(u64 a,u64 b,u64 c){ u64 d; asm("fma.rn.f32x2 %0,%1,%2,%3;":"=l"(d):"l"(a),"l"(b),"l"(c)); return d; }
__device__ __forceinline__ u64 add2(u64 a,u64 b){ u64 d; asm("add.rn.f32x2 %0,%1,%2;":"=l"(d):"l"(a),"l"(b)); return d; }
__device__ __forceinline__ uint32_t smem_u32(const void* p){
    uint32_t a; asm("{ .reg .u64 t; cvta.to.shared.u64 t, %1; cvt.u32.u64 %0, t; }":"=r"(a):"l"(p)); return a;
}
__device__ __forceinline__ void mma16816(float& c0, float& c1, float& c2, float& c3,
                                         uint32_t a0, uint32_t a1, uint32_t a2, uint32_t a3,
                                         uint32_t b0, uint32_t b1){
    asm volatile("mma.sync.aligned.m16n8k16.row.col.f32.bf16.bf16.f32 "
        "{%0,%1,%2,%3}, {%4,%5,%6,%7}, {%8,%9}, {%0,%1,%2,%3};"
        : "+f"(c0),"+f"(c1),"+f"(c2),"+f"(c3)
        : "r"(a0),"r"(a1),"r"(a2),"r"(a3),"r"(b0),"r"(b1));
}
__device__ __forceinline__ void ldm4(uint32_t& r0, uint32_t& r1, uint32_t& r2, uint32_t& r3, uint32_t a){
    asm volatile("ldmatrix.sync.aligned.m8n8.x4.shared.b16 {%0,%1,%2,%3}, [%4];"
        : "=r"(r0),"=r"(r1),"=r"(r2),"=r"(r3) : "r"(a));
}
__device__ __forceinline__ void split2(u64 p, uint32_t& hi, uint32_t& lo){
    float v0, v1; unpack2(p, v0, v1);
    v0 = fmaxf(v0, 0.f); v1 = fmaxf(v1, 0.f);
    __nv_bfloat16 h0 = __float2bfloat16(v0), h1 = __float2bfloat16(v1);
    __nv_bfloat16 l0 = __float2bfloat16(v0 - __bfloat162float(h0));
    __nv_bfloat16 l1 = __float2bfloat16(v1 - __bfloat162float(h1));
    hi = (uint32_t)__bfloat16_as_ushort(h0) | ((uint32_t)__bfloat16_as_ushort(h1) << 16);
    lo = (uint32_t)__bfloat16_as_ushort(l0) | ((uint32_t)__bfloat16_as_ushort(l1) << 16);
}

// SMEM byte offsets (phase1, 256-row CTA)
#define OAH 0u
#define OAL 36864u
#define OWH 73728u          // W tiles overlap the (dead-after-stepA) xs region
#define OWL 82944u
#define OXS 73728u          // 256 x 21 f32 = 21504 B
#define OW0 95232u
#define OB0 100352u
#define OBF 100608u
#define SMEM1 100864u

// ---------------- Prepack: Wf[:64] -> bf16 hi/lo words ----------------
__global__ void k_prep(const float* __restrict__ Wf)
{
    int idx = blockIdx.x * 256 + threadIdx.x;
    if (idx >= 2048) return;
    int c = idx >> 5, w = idx & 31;
    int k = 2 * w;
    float v0 = Wf[k * 64 + c];
    float v1 = Wf[(k + 1) * 64 + c];
    __nv_bfloat16 h0 = __float2bfloat16(v0), h1 = __float2bfloat16(v1);
    __nv_bfloat16 l0 = __float2bfloat16(v0 - __bfloat162float(h0));
    __nv_bfloat16 l1 = __float2bfloat16(v1 - __bfloat162float(h1));
    g_WpkH[idx] = (uint32_t)__bfloat16_as_ushort(h0) | ((uint32_t)__bfloat16_as_ushort(h1) << 16);
    g_WpkL[idx] = (uint32_t)__bfloat16_as_ushort(l0) | ((uint32_t)__bfloat16_as_ushort(l1) << 16);
}

// ---------------- Phase 1: FFMA step A + HMMA (bf16 3-split) ----------------
__global__ void __launch_bounds__(256, 2) k_phase1(
    const float* __restrict__ x, const float* __restrict__ W0,
    const float* __restrict__ b0, const float* __restrict__ bf)
{
    extern __shared__ char sm[];
    const uint32_t sb = smem_u32(sm);
    float* xs  = (float*)(sm + OXS);
    float* W0s = (float*)(sm + OW0);
    float* b0s = (float*)(sm + OB0);
    float* bfs = (float*)(sm + OBF);

    const int tid = threadIdx.x, wid = tid >> 5, lane = tid & 31;
    const int b = blockIdx.x;

    // coalesced x staging + small weights
    const float* xb = x + (size_t)b * T_ * D_;
    for (int i = tid; i < T_ * D_; i += 256) { int r = i / D_, d = i - r * D_; xs[r * 21 + d] = xb[i]; }
    for (int i = tid; i < D_ * E_; i += 256) W0s[i] = W0[i];
    if (tid < 64) { b0s[tid] = b0[tid]; bfs[tid] = bf[tid]; }
    __syncthreads();

    // ---- Step A: thread = one t-row, 64 cols ----
    {
        const int t = tid;
        u64 acc2[32];
        #pragma unroll
        for (int q = 0; q < 32; q++) acc2[q] = pack2(b0s[2*q], b0s[2*q+1]);
        #pragma unroll 4
        for (int d = 0; d < D_; d++) {
            float xv = xs[t * 21 + d];
            u64 xp = pack2(xv, xv);
            const ulonglong2* wr = (const ulonglong2*)&W0s[d * 64];
            #pragma unroll
            for (int q = 0; q < 16; q++) {
                ulonglong2 ww = wr[q];
                acc2[2*q]   = fma2(xp, ww.x, acc2[2*q]);
                acc2[2*q+1] = fma2(xp, ww.y, acc2[2*q+1]);
            }
        }
        __syncthreads();   // xs reads done (W tiles will overwrite xs region)
        #pragma unroll
        for (int q4 = 0; q4 < 8; q4++) {
            uint4 hv, lv;
            split2(acc2[4*q4+0], hv.x, lv.x);
            split2(acc2[4*q4+1], hv.y, lv.y);
            split2(acc2[4*q4+2], hv.z, lv.z);
            split2(acc2[4*q4+3], hv.w, lv.w);
            *(uint4*)(sm + OAH + t * 144 + q4 * 16) = hv;
            *(uint4*)(sm + OAL + t * 144 + q4 * 16) = lv;
        }
    }

    // ---- Copy prepacked W tiles (linear, conflict-free) ----
    for (int i = tid; i < 2048; i += 256) {
        int c = i >> 5, w = i & 31;
        *(uint32_t*)(sm + OWH + c * 144 + w * 4) = g_WpkH[i];
        *(uint32_t*)(sm + OWL + c * 144 + w * 4) = g_WpkL[i];
    }
    __syncthreads();

    // ---- Step B: warp = 32t x 64c, B frags via ldmatrix.x4 ----
    const int cb = (lane & 3) * 2;
    float acc[2][8][4];
    #pragma unroll
    for (int nt = 0; nt < 8; nt++) {
        float2 bv = *(float2*)&bfs[nt * 8 + cb];
        #pragma unroll
        for (int m = 0; m < 2; m++) {
            acc[m][nt][0] = bv.x; acc[m][nt][1] = bv.y;
            acc[m][nt][2] = bv.x; acc[m][nt][3] = bv.y;
        }
    }

    const int t0 = wid * 32;
    const int arow = ((lane >> 3) & 1) * 8 + (lane & 7);
    const int acol = (lane >> 4) * 16;
    const int seg = lane >> 3;
    const int brow = (lane & 7) + ((seg & 2) ? 8 : 0);   // row within 16-row pair
    const int bkof = (seg & 1) ? 16 : 0;                 // +8 k -> +16 bytes

    #pragma unroll
    for (int ks = 0; ks < 4; ks++) {
        const int k0 = ks * 16;
        uint32_t Ah[2][4], Al[2][4];
        #pragma unroll
        for (int mt = 0; mt < 2; mt++) {
            uint32_t ad = sb + OAH + (uint32_t)(t0 + mt * 16 + arow) * 144 + (uint32_t)(k0 * 2 + acol);
            ldm4(Ah[mt][0], Ah[mt][1], Ah[mt][2], Ah[mt][3], ad);
            ldm4(Al[mt][0], Al[mt][1], Al[mt][2], Al[mt][3], ad + (OAL - OAH));
        }
        #pragma unroll
        for (int p = 0; p < 4; p++) {
            uint32_t badr = sb + OWH + (uint32_t)(p * 16 + brow) * 144 + (uint32_t)(k0 * 2 + bkof);
            uint32_t bh0, bh1, bh2, bh3, bl0, bl1, bl2, bl3;
            ldm4(bh0, bh1, bh2, bh3, badr);
            ldm4(bl0, bl1, bl2, bl3, badr + (OWL - OWH));
            #pragma unroll
            for (int mt = 0; mt < 2; mt++) {
                mma16816(acc[mt][2*p][0], acc[mt][2*p][1], acc[mt][2*p][2], acc[mt][2*p][3],
                         Ah[mt][0], Ah[mt][1], Ah[mt][2], Ah[mt][3], bh0, bh1);
                mma16816(acc[mt][2*p][0], acc[mt][2*p][1], acc[mt][2*p][2], acc[mt][2*p][3],
                         Ah[mt][0], Ah[mt][1], Ah[mt][2], Ah[mt][3], bl0, bl1);
                mma16816(acc[mt][2*p][0], acc[mt][2*p][1], acc[mt][2*p][2], acc[mt][2*p][3],
                         Al[mt][0], Al[mt][1], Al[mt][2], Al[mt][3], bh0, bh1);
                mma16816(acc[mt][2*p+1][0], acc[mt][2*p+1][1], acc[mt][2*p+1][2], acc[mt][2*p+1][3],
                         Ah[mt][0], Ah[mt][1], Ah[mt][2], Ah[mt][3], bh2, bh3);
                mma16816(acc[mt][2*p+1][0], acc[mt][2*p+1][1], acc[mt][2*p+1][2], acc[mt][2*p+1][3],
                         Ah[mt][0], Ah[mt][1], Ah[mt][2], Ah[mt][3], bl2, bl3);
                mma16816(acc[mt][2*p+1][0], acc[mt][2*p+1][1], acc[mt][2*p+1][2], acc[mt][2*p+1][3],
                         Al[mt][0], Al[mt][1], Al[mt][2], Al[mt][3], bh2, bh3);
            }
        }
    }

    // ---- Direct fragment stores ----
    {
        float* Gb = g_G + (size_t)b * (G4_ * T_);
        #pragma unroll
        for (int mt = 0; mt < 2; mt++) {
            const int t = t0 + mt * 16 + (lane >> 2);
            #pragma unroll
            for (int nt = 0; nt < 8; nt++) {
                const int c = nt * 8 + cb;
                *(float2*)&Gb[(size_t)t * 64 + c]       = make_float2(acc[mt][nt][0], acc[mt][nt][1]);
                *(float2*)&Gb[(size_t)(t + 8) * 64 + c] = make_float2(acc[mt][nt][2], acc[mt][nt][3]);
            }
        }
    }
}

// ---------------- Phase 2: forward scan, tanh.approx activations ----------------
__global__ void __launch_bounds__(128) k_scan(const float* __restrict__ Wf)
{
    __shared__ float sg[4][2][8 * SGROW];

    const int tid = threadIdx.x, w = tid >> 5, l = tid & 31;
    const int b = blockIdx.x * 4 + w;
    const int j = l & 15;
    const int cA = (l < 16) ? l : (32 + j);
    const int cB = cA + 16;
    const int offA = cA + ((cA >> 5) << 4);
    const int offB = cB + ((cB >> 5) << 4);

    u64 wp[16];
    #pragma unroll
    for (int k = 0; k < 16; k++)
        wp[k] = pack2(Wf[(E_ + k) * G4_ + cA], Wf[(E_ + k) * G4_ + cB]);

    const float* Gb = g_G + (size_t)b * (G4_ * T_);

    int soff[4];
    #pragma unroll
    for (int k = 0; k < 4; k++) {
        int f  = l + 32 * k;
        int ti = f >> 4;
        int c4 = f & 15;
        soff[k] = ti * SGROW + c4 * 4 + ((c4 >> 3) << 4);
    }

    float h = 0.f, c = 0.f;

    // lanes<16: u=sig(i): 0.5+0.5*tanh(0.5 x); v=tanh(g)
    // lanes>=16: u=sig(f+1)=0.5+0.5*tanh(0.5x+0.5); v=sig(o)
    float bU, kV, aV, bV;
    if (l < 16) { bU = 0.f;  kV = 1.f;  aV = 1.f;  bV = 0.f;  }
    else        { bU = 0.5f; kV = 0.5f; aV = 0.5f; bV = 0.5f; }

    float4 r[4];
    {
        const float4* src = (const float4*)Gb;
        #pragma unroll
        for (int k = 0; k < 4; k++) r[k] = src[l + 32 * k];
        #pragma unroll
        for (int k = 0; k < 4; k++) *(float4*)&sg[w][0][soff[k]] = r[k];
    }
    __syncwarp();

    for (int tg = 0; tg < TGRP; ++tg) {
        const int buf = tg & 1;
        if (tg < TGRP - 1) {
            const float4* src = (const float4*)(Gb + (size_t)(tg + 1) * 512);
            #pragma unroll
            for (int k = 0; k < 4; k++) r[k] = src[l + 32 * k];
        }
        const float* sgb = &sg[w][buf][0];
        #pragma unroll
        for (int i = 0; i < 8; i++) {
            float ga = sgb[i * SGROW + offA];
            float gb = sgb[i * SGROW + offB];
            float h0  = __shfl_sync(0xffffffffu, h, 0);
            float h1  = __shfl_sync(0xffffffffu, h, 1);
            float h2  = __shfl_sync(0xffffffffu, h, 2);
            float h3  = __shfl_sync(0xffffffffu, h, 3);
            float h4  = __shfl_sync(0xffffffffu, h, 4);
            float h5  = __shfl_sync(0xffffffffu, h, 5);
            float h6  = __shfl_sync(0xffffffffu, h, 6);
            float h7  = __shfl_sync(0xffffffffu, h, 7);
            float h8  = __shfl_sync(0xffffffffu, h, 8);
            float h9  = __shfl_sync(0xffffffffu, h, 9);
            float h10 = __shfl_sync(0xffffffffu, h, 10);
            float h11 = __shfl_sync(0xffffffffu, h, 11);
            float h12 = __shfl_sync(0xffffffffu, h, 12);
            float h13 = __shfl_sync(0xffffffffu, h, 13);
            float h14 = __shfl_sync(0xffffffffu, h, 14);
            float h15 = __shfl_sync(0xffffffffu, h, 15);

            u64 a0p = pack2(ga, gb);
            a0p = fma2(pack2(h0, h0),   wp[0],  a0p);
            a0p = fma2(pack2(h1, h1),   wp[1],  a0p);
            a0p = fma2(pack2(h2, h2),   wp[2],  a0p);
            a0p = fma2(pack2(h3, h3),   wp[3],  a0p);
            u64 a1p = fma2(pack2(h4, h4),   wp[4],  0ULL);
            a1p = fma2(pack2(h5, h5),   wp[5],  a1p);
            a1p = fma2(pack2(h6, h6),   wp[6],  a1p);
            a1p = fma2(pack2(h7, h7),   wp[7],  a1p);
            u64 a2p = fma2(pack2(h8, h8),   wp[8],  0ULL);
            a2p = fma2(pack2(h9, h9),   wp[9],  a2p);
            a2p = fma2(pack2(h10, h10), wp[10], a2p);
            a2p = fma2(pack2(h11, h11), wp[11], a2p);
            u64 a3p = fma2(pack2(h12, h12), wp[12], 0ULL);
            a3p = fma2(pack2(h13, h13), wp[13], a3p);
            a3p = fma2(pack2(h14, h14), wp[14], a3p);
            a3p = fma2(pack2(h15, h15), wp[15], a3p);
            u64 acc = add2(add2(a0p, a1p), add2(a2p, a3p));
            float xA, xB; unpack2(acc, xA, xB);

            float u = fmaf(0.5f, tanha(fmaf(0.5f, xA, bU)), 0.5f);
            float v = fmaf(aV, tanha(kV * xB), bV);
            float sf = __shfl_down_sync(0xffffffffu, u, 16);
            float so = __shfl_down_sync(0xffffffffu, v, 16);
            if (l < 16) {
                c = fmaf(sf, c, u * v);
                h = so * tanha(c);
            }
        }
        if (tg < TGRP - 1) {
            #pragma unroll
            for (int k = 0; k < 4; k++) *(float4*)&sg[w][buf ^ 1][soff[k]] = r[k];
            __syncwarp();
        }
    }
    if (l < 16) g_hf[b * H_ + l] = h;
}

// ---------------- Tail: bwd single step + head MLP ----------------
__global__ void __launch_bounds__(256) k_tail(
    const float* __restrict__ x, const float* __restrict__ W0,
    const float* __restrict__ b0, const float* __restrict__ Wb,
    const float* __restrict__ bb,
    const float* __restrict__ W1, const float* __restrict__ b1,
    const float* __restrict__ W2, const float* __restrict__ b2,
    const float* __restrict__ W3, const float* __restrict__ b3,
    float* __restrict__ out)
{
    __shared__ float W0s[D_ * E_];
    __shared__ float Wbs[E_ * G4_];
    __shared__ float b0s[64], bbs[64];
    __shared__ float W1s[32 * 64], W2s[64 * 16], W3s[32];
    __shared__ float b1s[64], b2s[16], b3s[2];
    __shared__ float xsh[8][20];
    __shared__ __align__(16) float2 hes[8][64];
    __shared__ float hbs[8][16];
    __shared__ float insh[8][32], ush[8][64], vsh[8][16];

    const int tid = threadIdx.x, w = tid >> 5, l = tid & 31;
    const int b = blockIdx.x * 8 + w;

    for (int i = tid; i < D_ * E_;  i += 256) W0s[i] = W0[i];
    for (int i = tid; i < E_ * G4_; i += 256) Wbs[i] = Wb[i];
    for (int i = tid; i < 32 * 64;  i += 256) W1s[i] = W1[i];
    for (int i = tid; i < 64 * 16;  i += 256) W2s[i] = W2[i];
    if (tid < 32) W3s[tid] = W3[tid];
    if (tid < 64) { b0s[tid] = b0[tid]; bbs[tid] = bb[tid]; b1s[tid] = b1[tid]; }
    if (tid < 16) b2s[tid] = b2[tid];
    if (tid < 2)  b3s[tid] = b3[tid];
    __syncthreads();

    if (l < 20) xsh[w][l] = x[((size_t)b * T_ + (T_ - 1)) * D_ + l];
    __syncwarp();

    float a0 = b0s[l], a1 = b0s[l + 32];
    #pragma unroll
    for (int d = 0; d < D_; d++) {
        float xv = xsh[w][d];
        a0 = fmaf(xv, W0s[d * E_ + l],      a0);
        a1 = fmaf(xv, W0s[d * E_ + l + 32], a1);
    }
    a0 = fmaxf(a0, 0.f); a1 = fmaxf(a1, 0.f);
    hes[w][l]      = make_float2(a0, a0);
    hes[w][l + 32] = make_float2(a1, a1);
    __syncwarp();

    const int j = l & 15;
    const int cA = (l < 16) ? l : (32 + j);
    const int cB = cA + 16;
    u64 acc = pack2(bbs[cA], bbs[cB]);
    #pragma unroll 8
    for (int k = 0; k < E_; k++) {
        u64 hd = *(const u64*)&hes[w][k];
        acc = fma2(hd, pack2(Wbs[k * G4_ + cA], Wbs[k * G4_ + cB]), acc);
    }
    float xA, xB; unpack2(acc, xA, xB);

    float bU, kV, aV, bV;
    if (l < 16) { bU = 0.f;  kV = 1.f;  aV = 1.f;  bV = 0.f;  }
    else        { bU = 0.5f; kV = 0.5f; aV = 0.5f; bV = 0.5f; }
    float u = fmaf(0.5f, tanha(fmaf(0.5f, xA, bU)), 0.5f);
    float v = fmaf(aV, tanha(kV * xB), bV);
    float so = __shfl_down_sync(0xffffffffu, v, 16);
    if (l < 16) {
        float cc = u * v;
        hbs[w][l] = so * tanha(cc);
    }
    __syncwarp();

    insh[w][l] = (l < 16) ? g_hf[b * H_ + l] : hbs[w][l - 16];
    __syncwarp();

    float u0 = b1s[l], u1 = b1s[l + 32];
    #pragma unroll 8
    for (int k = 0; k < 32; k++) {
        float t = insh[w][k];
        u0 = fmaf(t, W1s[k * 64 + l],      u0);
        u1 = fmaf(t, W1s[k * 64 + l + 32], u1);
    }
    ush[w][l]      = fmaxf(u0, 0.f);
    ush[w][l + 32] = fmaxf(u1, 0.f);
    __syncwarp();

    if (l < 16) {
        float a = b2s[l];
        #pragma unroll 8
        for (int k = 0; k < 64; k++) a = fmaf(ush[w][k], W2s[k * 16 + l], a);
        vsh[w][l] = fmaxf(a, 0.f);
    }
    __syncwarp();

    if (l < 2) {
        float a = b3s[l];
        #pragma unroll
        for (int k = 0; k < 16; k++) a = fmaf(vsh[w][k], W3s[k * 2 + l], a);
        out[b * 2 + l] = a;
    }
}

extern "C" void kernel_launch(void* const* d_in, const int* in_sizes, int n_in,
                              void* d_out, int out_size)
{
    (void)in_sizes; (void)n_in; (void)out_size;
    const float* x  = (const float*)d_in[0];
    const float* W0 = (const float*)d_in[1];
    const float* b0 = (const float*)d_in[2];
    const float* Wf = (const float*)d_in[3];
    const float* bf = (const float*)d_in[4];
    const float* Wb = (const float*)d_in[5];
    const float* bb = (const float*)d_in[6];
    const float* W1 = (const float*)d_in[7];
    const float* b1 = (const float*)d_in[8];
    const float* W2 = (const float*)d_in[9];
    const float* b2 = (const float*)d_in[10];
    const float* W3 = (const float*)d_in[11];
    const float* b3 = (const float*)d_in[12];
    float* out = (float*)d_out;

    cudaFuncSetAttribute(k_phase1, cudaFuncAttributeMaxDynamicSharedMemorySize, (int)SMEM1);

    k_prep  <<<8, 256>>>(Wf);
    k_phase1<<<B_,     256, SMEM1>>>(x, W0, b0, bf);
    k_scan  <<<B_ / 4, 128>>>(Wf);
    k_tail  <<<B_ / 8, 256>>>(x, W0, b0, Wb, bb, W1, b1, W2, b2, W3, b3, out);
}

// round 9
// speedup vs baseline: 1.3136x; 1.1586x over previous
#include <cuda_runtime.h>
#include <cuda_bf16.h>
#include <cstdint>

#define B_  4096
#define T_  256
#define D_  20
#define E_  64
#define H_  16
#define G4_ 64
#define TGRP 32
#define SGROW 80

// G layout: [b][t(256)][c(64)]
__device__ float g_G[(size_t)B_ * G4_ * T_];
__device__ float g_hf[B_ * H_];

typedef unsigned long long u64;

__device__ __forceinline__ float tanha(float x){ float y; asm("tanh.approx.f32 %0,%1;":"=f"(y):"f"(x)); return y; }
__device__ __forceinline__ u64 pack2(float a,float b){ u64 r; asm("mov.b64 %0,{%1,%2};":"=l"(r):"f"(a),"f"(b)); return r; }
__device__ __forceinline__ void unpack2(u64 v,float&a,float&b){ asm("mov.b64 {%0,%1},%2;":"=f"(a),"=f"(b):"l"(v)); }
__device__ __forceinline__ u64 fma2(u64 a,u64 b,u64 c){ u64 d; asm("fma.rn.f32x2 %0,%1,%2,%3;":"=l"(d):"l"(a),"l"(b),"l"(c)); return d; }
__device__ __forceinline__ u64 add2(u64 a,u64 b){ u64 d; asm("add.rn.f32x2 %0,%1,%2;":"=l"(d):"l"(a),"l"(b)); return d; }
__device__ __forceinline__ uint32_t smem_u32(const void* p){
    uint32_t a; asm("{ .reg .u64 t; cvta.to.shared.u64 t, %1; cvt.u32.u64 %0, t; }":"=r"(a):"l"(p)); return a;
}
__device__ __forceinline__ void mma16816(float& c0, float& c1, float& c2, float& c3,
                                         uint32_t a0, uint32_t a1, uint32_t a2, uint32_t a3,
                                         uint32_t b0, uint32_t b1){
    asm volatile("mma.sync.aligned.m16n8k16.row.col.f32.bf16.bf16.f32 "
        "{%0,%1,%2,%3}, {%4,%5,%6,%7}, {%8,%9}, {%0,%1,%2,%3};"
        : "+f"(c0),"+f"(c1),"+f"(c2),"+f"(c3)
        : "r"(a0),"r"(a1),"r"(a2),"r"(a3),"r"(b0),"r"(b1));
}
__device__ __forceinline__ void ldm4(uint32_t& r0, uint32_t& r1, uint32_t& r2, uint32_t& r3, uint32_t a){
    asm volatile("ldmatrix.sync.aligned.m8n8.x4.shared.b16 {%0,%1,%2,%3}, [%4];"
        : "=r"(r0),"=r"(r1),"=r"(r2),"=r"(r3) : "r"(a));
}
__device__ __forceinline__ void split2(u64 p, uint32_t& hi, uint32_t& lo){
    float v0, v1; unpack2(p, v0, v1);
    v0 = fmaxf(v0, 0.f); v1 = fmaxf(v1, 0.f);
    __nv_bfloat16 h0 = __float2bfloat16(v0), h1 = __float2bfloat16(v1);
    __nv_bfloat16 l0 = __float2bfloat16(v0 - __bfloat162float(h0));
    __nv_bfloat16 l1 = __float2bfloat16(v1 - __bfloat162float(h1));
    hi = (uint32_t)__bfloat16_as_ushort(h0) | ((uint32_t)__bfloat16_as_ushort(h1) << 16);
    lo = (uint32_t)__bfloat16_as_ushort(l0) | ((uint32_t)__bfloat16_as_ushort(l1) << 16);
}

// SMEM byte offsets (phase1) — R6 layout
#define OAH 0u
#define OAL 36864u
#define OWH 73728u
#define OWL 82944u
#define OW0 92160u
#define OB0 97280u
#define OBF 97536u
#define SMEM1 97792u

// ---------------- Phase 1: R6-exact (best measured: 248us) ----------------
__global__ void __launch_bounds__(256, 2) k_phase1(
    const float* __restrict__ x, const float* __restrict__ W0,
    const float* __restrict__ b0, const float* __restrict__ Wf,
    const float* __restrict__ bf)
{
    extern __shared__ char sm[];
    const uint32_t sb = smem_u32(sm);
    float* W0s = (float*)(sm + OW0);
    float* b0s = (float*)(sm + OB0);
    float* bfs = (float*)(sm + OBF);

    const int tid = threadIdx.x, wid = tid >> 5, lane = tid & 31;
    const int b = blockIdx.x;

    for (int i = tid; i < D_ * E_; i += 256) W0s[i] = W0[i];
    if (tid < 64) { b0s[tid] = b0[tid]; bfs[tid] = bf[tid]; }
    for (int i = tid; i < 4096; i += 256) {
        int k = i >> 6, c = i & 63;
        float v = Wf[i];
        __nv_bfloat16 h = __float2bfloat16(v);
        __nv_bfloat16 l = __float2bfloat16(v - __bfloat162float(h));
        *(unsigned short*)(sm + OWH + c * 144 + k * 2) = __bfloat16_as_ushort(h);
        *(unsigned short*)(sm + OWL + c * 144 + k * 2) = __bfloat16_as_ushort(l);
    }
    __syncthreads();

    // ---- Step A ----
    {
        const int t = tid;
        const float4* xp4 = (const float4*)(x + (size_t)b * (T_ * D_) + t * D_);
        float xv[20];
        #pragma unroll
        for (int q = 0; q < 5; q++) {
            float4 f = __ldg(xp4 + q);
            xv[4*q] = f.x; xv[4*q+1] = f.y; xv[4*q+2] = f.z; xv[4*q+3] = f.w;
        }
        u64 acc2[32];
        #pragma unroll
        for (int q = 0; q < 32; q++) acc2[q] = pack2(b0s[2*q], b0s[2*q+1]);
        #pragma unroll 4
        for (int d = 0; d < D_; d++) {
            u64 xp = pack2(xv[d], xv[d]);
            const ulonglong2* wr = (const ulonglong2*)&W0s[d * 64];
            #pragma unroll
            for (int q = 0; q < 16; q++) {
                ulonglong2 ww = wr[q];
                acc2[2*q]   = fma2(xp, ww.x, acc2[2*q]);
                acc2[2*q+1] = fma2(xp, ww.y, acc2[2*q+1]);
            }
        }
        #pragma unroll
        for (int q4 = 0; q4 < 8; q4++) {
            uint4 hv, lv;
            split2(acc2[4*q4+0], hv.x, lv.x);
            split2(acc2[4*q4+1], hv.y, lv.y);
            split2(acc2[4*q4+2], hv.z, lv.z);
            split2(acc2[4*q4+3], hv.w, lv.w);
            *(uint4*)(sm + OAH + t * 144 + q4 * 16) = hv;
            *(uint4*)(sm + OAL + t * 144 + q4 * 16) = lv;
        }
    }
    __syncthreads();

    // ---- Step B ----
    float acc[2][8][4];
    {
        const int cb = (lane & 3) * 2;
        #pragma unroll
        for (int nt = 0; nt < 8; nt++) {
            float2 bv = *(float2*)&bfs[nt * 8 + cb];
            #pragma unroll
            for (int m = 0; m < 2; m++) {
                acc[m][nt][0] = bv.x; acc[m][nt][1] = bv.y;
                acc[m][nt][2] = bv.x; acc[m][nt][3] = bv.y;
            }
        }
    }

    const int t0 = wid * 32;
    const int arow = ((lane >> 3) & 1) * 8 + (lane & 7);
    const int acol = (lane >> 4) * 16;

    #pragma unroll
    for (int ks = 0; ks < 4; ks++) {
        const int k0 = ks * 16;
        uint32_t Ah[2][4], Al[2][4];
        #pragma unroll
        for (int mt = 0; mt < 2; mt++) {
            uint32_t ad = sb + OAH + (uint32_t)(t0 + mt * 16 + arow) * 144 + (uint32_t)(k0 * 2 + acol);
            ldm4(Ah[mt][0], Ah[mt][1], Ah[mt][2], Ah[mt][3], ad);
            ldm4(Al[mt][0], Al[mt][1], Al[mt][2], Al[mt][3], ad + (OAL - OAH));
        }
        #pragma unroll
        for (int nt = 0; nt < 8; nt++) {
            const uint32_t boff = (uint32_t)((nt * 8 + (lane >> 2)) * 144 + k0 * 2 + (lane & 3) * 4);
            uint32_t bh0 = *(const uint32_t*)(sm + OWH + boff);
            uint32_t bh1 = *(const uint32_t*)(sm + OWH + boff + 16);
            uint32_t bl0 = *(const uint32_t*)(sm + OWL + boff);
            uint32_t bl1 = *(const uint32_t*)(sm + OWL + boff + 16);
            #pragma unroll
            for (int mt = 0; mt < 2; mt++) {
                mma16816(acc[mt][nt][0], acc[mt][nt][1], acc[mt][nt][2], acc[mt][nt][3],
                         Ah[mt][0], Ah[mt][1], Ah[mt][2], Ah[mt][3], bh0, bh1);
                mma16816(acc[mt][nt][0], acc[mt][nt][1], acc[mt][nt][2], acc[mt][nt][3],
                         Ah[mt][0], Ah[mt][1], Ah[mt][2], Ah[mt][3], bl0, bl1);
                mma16816(acc[mt][nt][0], acc[mt][nt][1], acc[mt][nt][2], acc[mt][nt][3],
                         Al[mt][0], Al[mt][1], Al[mt][2], Al[mt][3], bh0, bh1);
            }
        }
    }

    // ---- Direct fragment stores ----
    {
        float* Gb = g_G + (size_t)b * (G4_ * T_);
        const int cb = (lane & 3) * 2;
        #pragma unroll
        for (int mt = 0; mt < 2; mt++) {
            const int t = t0 + mt * 16 + (lane >> 2);
            #pragma unroll
            for (int nt = 0; nt < 8; nt++) {
                const int c = nt * 8 + cb;
                *(float2*)&Gb[(size_t)t * 64 + c]       = make_float2(acc[mt][nt][0], acc[mt][nt][1]);
                *(float2*)&Gb[(size_t)(t + 8) * 64 + c] = make_float2(acc[mt][nt][2], acc[mt][nt][3]);
            }
        }
    }
}

// ---------------- Phase 2: scan (R6 structure + tanh.approx activations) ----------------
__global__ void __launch_bounds__(128) k_scan(const float* __restrict__ Wf)
{
    __shared__ float sg[4][2][8 * SGROW];

    const int tid = threadIdx.x, w = tid >> 5, l = tid & 31;
    const int b = blockIdx.x * 4 + w;
    const int j = l & 15;
    const int cA = (l < 16) ? l : (32 + j);
    const int cB = cA + 16;
    const int offA = cA + ((cA >> 5) << 4);
    const int offB = cB + ((cB >> 5) << 4);

    u64 wp[16];
    #pragma unroll
    for (int k = 0; k < 16; k++)
        wp[k] = pack2(Wf[(E_ + k) * G4_ + cA], Wf[(E_ + k) * G4_ + cB]);

    const float* Gb = g_G + (size_t)b * (G4_ * T_);

    int soff[4];
    #pragma unroll
    for (int k = 0; k < 4; k++) {
        int f  = l + 32 * k;
        int ti = f >> 4;
        int c4 = f & 15;
        soff[k] = ti * SGROW + c4 * 4 + ((c4 >> 3) << 4);
    }

    float h = 0.f, c = 0.f;

    // lanes<16: u=sig(i)=0.5+0.5*tanh(0.5x); v=tanh(g)
    // lanes>=16: u=sig(f+1)=0.5+0.5*tanh(0.5x+0.5); v=sig(o)
    float bU, kV, aV, bV;
    if (l < 16) { bU = 0.f;  kV = 1.f;  aV = 1.f;  bV = 0.f;  }
    else        { bU = 0.5f; kV = 0.5f; aV = 0.5f; bV = 0.5f; }

    float4 r[4];
    {
        const float4* src = (const float4*)Gb;
        #pragma unroll
        for (int k = 0; k < 4; k++) r[k] = src[l + 32 * k];
        #pragma unroll
        for (int k = 0; k < 4; k++) *(float4*)&sg[w][0][soff[k]] = r[k];
    }
    __syncwarp();

    for (int tg = 0; tg < TGRP; ++tg) {
        const int buf = tg & 1;
        if (tg < TGRP - 1) {
            const float4* src = (const float4*)(Gb + (size_t)(tg + 1) * 512);
            #pragma unroll
            for (int k = 0; k < 4; k++) r[k] = src[l + 32 * k];
        }
        const float* sgb = &sg[w][buf][0];
        #pragma unroll
        for (int i = 0; i < 8; i++) {
            float ga = sgb[i * SGROW + offA];
            float gb = sgb[i * SGROW + offB];
            float h0  = __shfl_sync(0xffffffffu, h, 0);
            float h1  = __shfl_sync(0xffffffffu, h, 1);
            float h2  = __shfl_sync(0xffffffffu, h, 2);
            float h3  = __shfl_sync(0xffffffffu, h, 3);
            float h4  = __shfl_sync(0xffffffffu, h, 4);
            float h5  = __shfl_sync(0xffffffffu, h, 5);
            float h6  = __shfl_sync(0xffffffffu, h, 6);
            float h7  = __shfl_sync(0xffffffffu, h, 7);
            float h8  = __shfl_sync(0xffffffffu, h, 8);
            float h9  = __shfl_sync(0xffffffffu, h, 9);
            float h10 = __shfl_sync(0xffffffffu, h, 10);
            float h11 = __shfl_sync(0xffffffffu, h, 11);
            float h12 = __shfl_sync(0xffffffffu, h, 12);
            float h13 = __shfl_sync(0xffffffffu, h, 13);
            float h14 = __shfl_sync(0xffffffffu, h, 14);
            float h15 = __shfl_sync(0xffffffffu, h, 15);

            u64 a0p = pack2(ga, gb);
            a0p = fma2(pack2(h0, h0),   wp[0],  a0p);
            a0p = fma2(pack2(h1, h1),   wp[1],  a0p);
            a0p = fma2(pack2(h2, h2),   wp[2],  a0p);
            a0p = fma2(pack2(h3, h3),   wp[3],  a0p);
            u64 a1p = fma2(pack2(h4, h4),   wp[4],  0ULL);
            a1p = fma2(pack2(h5, h5),   wp[5],  a1p);
            a1p = fma2(pack2(h6, h6),   wp[6],  a1p);
            a1p = fma2(pack2(h7, h7),   wp[7],  a1p);
            u64 a2p = fma2(pack2(h8, h8),   wp[8],  0ULL);
            a2p = fma2(pack2(h9, h9),   wp[9],  a2p);
            a2p = fma2(pack2(h10, h10), wp[10], a2p);
            a2p = fma2(pack2(h11, h11), wp[11], a2p);
            u64 a3p = fma2(pack2(h12, h12), wp[12], 0ULL);
            a3p = fma2(pack2(h13, h13), wp[13], a3p);
            a3p = fma2(pack2(h14, h14), wp[14], a3p);
            a3p = fma2(pack2(h15, h15), wp[15], a3p);
            u64 acc = add2(add2(a0p, a1p), add2(a2p, a3p));
            float xA, xB; unpack2(acc, xA, xB);

            float u = fmaf(0.5f, tanha(fmaf(0.5f, xA, bU)), 0.5f);
            float v = fmaf(aV, tanha(kV * xB), bV);
            float sf = __shfl_down_sync(0xffffffffu, u, 16);
            float so = __shfl_down_sync(0xffffffffu, v, 16);
            if (l < 16) {
                c = fmaf(sf, c, u * v);
                h = so * tanha(c);
            }
        }
        if (tg < TGRP - 1) {
            #pragma unroll
            for (int k = 0; k < 4; k++) *(float4*)&sg[w][buf ^ 1][soff[k]] = r[k];
            __syncwarp();
        }
    }
    if (l < 16) g_hf[b * H_ + l] = h;
}

// ---------------- Tail: bwd single step + head MLP (R6-exact + tanh) ----------------
__global__ void __launch_bounds__(256) k_tail(
    const float* __restrict__ x, const float* __restrict__ W0,
    const float* __restrict__ b0, const float* __restrict__ Wb,
    const float* __restrict__ bb,
    const float* __restrict__ W1, const float* __restrict__ b1,
    const float* __restrict__ W2, const float* __restrict__ b2,
    const float* __restrict__ W3, const float* __restrict__ b3,
    float* __restrict__ out)
{
    __shared__ float W0s[D_ * E_];
    __shared__ float Wbs[E_ * G4_];
    __shared__ float b0s[64], bbs[64];
    __shared__ float W1s[32 * 64], W2s[64 * 16], W3s[32];
    __shared__ float b1s[64], b2s[16], b3s[2];
    __shared__ float xsh[8][20];
    __shared__ __align__(16) float2 hes[8][64];
    __shared__ float hbs[8][16];
    __shared__ float insh[8][32], ush[8][64], vsh[8][16];

    const int tid = threadIdx.x, w = tid >> 5, l = tid & 31;
    const int b = blockIdx.x * 8 + w;

    for (int i = tid; i < D_ * E_;  i += 256) W0s[i] = W0[i];
    for (int i = tid; i < E_ * G4_; i += 256) Wbs[i] = Wb[i];
    for (int i = tid; i < 32 * 64;  i += 256) W1s[i] = W1[i];
    for (int i = tid; i < 64 * 16;  i += 256) W2s[i] = W2[i];
    if (tid < 32) W3s[tid] = W3[tid];
    if (tid < 64) { b0s[tid] = b0[tid]; bbs[tid] = bb[tid]; b1s[tid] = b1[tid]; }
    if (tid < 16) b2s[tid] = b2[tid];
    if (tid < 2)  b3s[tid] = b3[tid];
    __syncthreads();

    if (l < 20) xsh[w][l] = x[((size_t)b * T_ + (T_ - 1)) * D_ + l];
    __syncwarp();

    float a0 = b0s[l], a1 = b0s[l + 32];
    #pragma unroll
    for (int d = 0; d < D_; d++) {
        float xv = xsh[w][d];
        a0 = fmaf(xv, W0s[d * E_ + l],      a0);
        a1 = fmaf(xv, W0s[d * E_ + l + 32], a1);
    }
    a0 = fmaxf(a0, 0.f); a1 = fmaxf(a1, 0.f);
    hes[w][l]      = make_float2(a0, a0);
    hes[w][l + 32] = make_float2(a1, a1);
    __syncwarp();

    const int j = l & 15;
    const int cA = (l < 16) ? l : (32 + j);
    const int cB = cA + 16;
    u64 acc = pack2(bbs[cA], bbs[cB]);
    #pragma unroll 8
    for (int k = 0; k < E_; k++) {
        u64 hd = *(const u64*)&hes[w][k];
        acc = fma2(hd, pack2(Wbs[k * G4_ + cA], Wbs[k * G4_ + cB]), acc);
    }
    float xA, xB; unpack2(acc, xA, xB);

    float bU, kV, aV, bV;
    if (l < 16) { bU = 0.f;  kV = 1.f;  aV = 1.f;  bV = 0.f;  }
    else        { bU = 0.5f; kV = 0.5f; aV = 0.5f; bV = 0.5f; }
    float u = fmaf(0.5f, tanha(fmaf(0.5f, xA, bU)), 0.5f);
    float v = fmaf(aV, tanha(kV * xB), bV);
    float so = __shfl_down_sync(0xffffffffu, v, 16);
    if (l < 16) {
        float cc = u * v;
        hbs[w][l] = so * tanha(cc);
    }
    __syncwarp();

    insh[w][l] = (l < 16) ? g_hf[b * H_ + l] : hbs[w][l - 16];
    __syncwarp();

    float u0 = b1s[l], u1 = b1s[l + 32];
    #pragma unroll 8
    for (int k = 0; k < 32; k++) {
        float t = insh[w][k];
        u0 = fmaf(t, W1s[k * 64 + l],      u0);
        u1 = fmaf(t, W1s[k * 64 + l + 32], u1);
    }
    ush[w][l]      = fmaxf(u0, 0.f);
    ush[w][l + 32] = fmaxf(u1, 0.f);
    __syncwarp();

    if (l < 16) {
        float a = b2s[l];
        #pragma unroll 8
        for (int k = 0; k < 64; k++) a = fmaf(ush[w][k], W2s[k * 16 + l], a);
        vsh[w][l] = fmaxf(a, 0.f);
    }
    __syncwarp();

    if (l < 2) {
        float a = b3s[l];
        #pragma unroll
        for (int k = 0; k < 16; k++) a = fmaf(vsh[w][k], W3s[k * 2 + l], a);
        out[b * 2 + l] = a;
    }
}

extern "C" void kernel_launch(void* const* d_in, const int* in_sizes, int n_in,
                              void* d_out, int out_size)
{
    (void)in_sizes; (void)n_in; (void)out_size;
    const float* x  = (const float*)d_in[0];
    const float* W0 = (const float*)d_in[1];
    const float* b0 = (const float*)d_in[2];
    const float* Wf = (const float*)d_in[3];
    const float* bf = (const float*)d_in[4];
    const float* Wb = (const float*)d_in[5];
    const float* bb = (const float*)d_in[6];
    const float* W1 = (const float*)d_in[7];
    const float* b1 = (const float*)d_in[8];
    const float* W2 = (const float*)d_in[9];
    const float* b2 = (const float*)d_in[10];
    const float* W3 = (const float*)d_in[11];
    const float* b3 = (const float*)d_in[12];
    float* out = (float*)d_out;

    cudaFuncSetAttribute(k_phase1, cudaFuncAttributeMaxDynamicSharedMemorySize, (int)SMEM1);

    k_phase1<<<B_,     256, SMEM1>>>(x, W0, b0, Wf, bf);
    k_scan  <<<B_ / 4, 128>>>(Wf);
    k_tail  <<<B_ / 8, 256>>>(x, W0, b0, Wb, bb, W1, b1, W2, b2, W3, b3, out);
}

// round 11
// speedup vs baseline: 1.4485x; 1.1027x over previous
#include <cuda_runtime.h>
#include <cuda_bf16.h>
#include <cstdint>

#define B_  4096
#define T_  256
#define D_  20
#define E_  64
#define H_  16
#define G4_ 64
#define TGRP 32
#define SGROW 80

// G layout: [b][t(256)][c(64)]
__device__ float g_G[(size_t)B_ * G4_ * T_];
__device__ float g_hf[B_ * H_];
// Prepacked WfT bf16 hi/lo tiles, EXACT smem layout (64 rows x 144B = 9216 B each)
__device__ __align__(16) unsigned char g_WfH[9216];
__device__ __align__(16) unsigned char g_WfL[9216];

typedef unsigned long long u64;

__device__ __forceinline__ float tanha(float x){ float y; asm("tanh.approx.f32 %0,%1;":"=f"(y):"f"(x)); return y; }
__device__ __forceinline__ u64 pack2(float a,float b){ u64 r; asm("mov.b64 %0,{%1,%2};":"=l"(r):"f"(a),"f"(b)); return r; }
__device__ __forceinline__ void unpack2(u64 v,float&a,float&b){ asm("mov.b64 {%0,%1},%2;":"=f"(a),"=f"(b):"l"(v)); }
__device__ __forceinline__ u64 fma2(u64 a,u64 b,u64 c){ u64 d; asm("fma.rn.f32x2 %0,%1,%2,%3;":"=l"(d):"l"(a),"l"(b),"l"(c)); return d; }
__device__ __forceinline__ u64 add2(u64 a,u64 b){ u64 d; asm("add.rn.f32x2 %0,%1,%2;":"=l"(d):"l"(a),"l"(b)); return d; }
__device__ __forceinline__ uint32_t smem_u32(const void* p){
    uint32_t a; asm("{ .reg .u64 t; cvta.to.shared.u64 t, %1; cvt.u32.u64 %0, t; }":"=r"(a):"l"(p)); return a;
}
__device__ __forceinline__ void mma16816(float& c0, float& c1, float& c2, float& c3,
                                         uint32_t a0, uint32_t a1, uint32_t a2, uint32_t a3,
                                         uint32_t b0, uint32_t b1){
    asm volatile("mma.sync.aligned.m16n8k16.row.col.f32.bf16.bf16.f32 "
        "{%0,%1,%2,%3}, {%4,%5,%6,%7}, {%8,%9}, {%0,%1,%2,%3};"
        : "+f"(c0),"+f"(c1),"+f"(c2),"+f"(c3)
        : "r"(a0),"r"(a1),"r"(a2),"r"(a3),"r"(b0),"r"(b1));
}
__device__ __forceinline__ void ldm4(uint32_t& r0, uint32_t& r1, uint32_t& r2, uint32_t& r3, uint32_t a){
    asm volatile("ldmatrix.sync.aligned.m8n8.x4.shared.b16 {%0,%1,%2,%3}, [%4];"
        : "=r"(r0),"=r"(r1),"=r"(r2),"=r"(r3) : "r"(a));
}
__device__ __forceinline__ void split2(u64 p, uint32_t& hi, uint32_t& lo){
    float v0, v1; unpack2(p, v0, v1);
    v0 = fmaxf(v0, 0.f); v1 = fmaxf(v1, 0.f);
    __nv_bfloat16 h0 = __float2bfloat16(v0), h1 = __float2bfloat16(v1);
    __nv_bfloat16 l0 = __float2bfloat16(v0 - __bfloat162float(h0));
    __nv_bfloat16 l1 = __float2bfloat16(v1 - __bfloat162float(h1));
    hi = (uint32_t)__bfloat16_as_ushort(h0) | ((uint32_t)__bfloat16_as_ushort(h1) << 16);
    lo = (uint32_t)__bfloat16_as_ushort(l0) | ((uint32_t)__bfloat16_as_ushort(l1) << 16);
}

// SMEM byte offsets (phase1) — R6/R9 layout
#define OAH 0u
#define OAL 36864u
#define OWH 73728u
#define OWL 82944u
#define OW0 92160u
#define OB0 97280u
#define OBF 97536u
#define SMEM1 97792u

// ---------------- Prepack: Wf[:64] -> bf16 hi/lo tiles in smem layout ----------------
__global__ void k_prep(const float* __restrict__ Wf)
{
    int i = blockIdx.x * 256 + threadIdx.x;        // 0..4095
    if (i >= 4096) return;
    int k = i >> 6, c = i & 63;
    float v = Wf[i];
    __nv_bfloat16 h = __float2bfloat16(v);
    __nv_bfloat16 l = __float2bfloat16(v - __bfloat162float(h));
    *(unsigned short*)(g_WfH + c * 144 + k * 2) = __bfloat16_as_ushort(h);
    *(unsigned short*)(g_WfL + c * 144 + k * 2) = __bfloat16_as_ushort(l);
    // zero row padding bytes [128,144)
    if (i < 64) {
        *(uint4*)(g_WfH + i * 144 + 128) = make_uint4(0,0,0,0);
        *(uint4*)(g_WfL + i * 144 + 128) = make_uint4(0,0,0,0);
    }
}

// ---------------- Phase 1: R9-exact except W tiles copied linearly ----------------
__global__ void __launch_bounds__(256, 2) k_phase1(
    const float* __restrict__ x, const float* __restrict__ W0,
    const float* __restrict__ b0, const float* __restrict__ bf)
{
    extern __shared__ char sm[];
    const uint32_t sb = smem_u32(sm);
    float* W0s = (float*)(sm + OW0);
    float* b0s = (float*)(sm + OB0);
    float* bfs = (float*)(sm + OBF);

    const int tid = threadIdx.x, wid = tid >> 5, lane = tid & 31;
    const int b = blockIdx.x;

    for (int i = tid; i < D_ * E_; i += 256) W0s[i] = W0[i];
    if (tid < 64) { b0s[tid] = b0[tid]; bfs[tid] = bf[tid]; }
    // linear conflict-free copy of prepacked W tiles: 576 uint4 each
    {
        const uint4* srcH = (const uint4*)g_WfH;
        const uint4* srcL = (const uint4*)g_WfL;
        #pragma unroll
        for (int q = 0; q < 3; q++) {
            int i = tid + q * 256;
            if (i < 576) {
                *(uint4*)(sm + OWH + i * 16) = srcH[i];
                *(uint4*)(sm + OWL + i * 16) = srcL[i];
            }
        }
    }
    __syncthreads();

    // ---- Step A ----
    {
        const int t = tid;
        const float4* xp4 = (const float4*)(x + (size_t)b * (T_ * D_) + t * D_);
        float xv[20];
        #pragma unroll
        for (int q = 0; q < 5; q++) {
            float4 f = __ldg(xp4 + q);
            xv[4*q] = f.x; xv[4*q+1] = f.y; xv[4*q+2] = f.z; xv[4*q+3] = f.w;
        }
        u64 acc2[32];
        #pragma unroll
        for (int q = 0; q < 32; q++) acc2[q] = pack2(b0s[2*q], b0s[2*q+1]);
        #pragma unroll 4
        for (int d = 0; d < D_; d++) {
            u64 xp = pack2(xv[d], xv[d]);
            const ulonglong2* wr = (const ulonglong2*)&W0s[d * 64];
            #pragma unroll
            for (int q = 0; q < 16; q++) {
                ulonglong2 ww = wr[q];
                acc2[2*q]   = fma2(xp, ww.x, acc2[2*q]);
                acc2[2*q+1] = fma2(xp, ww.y, acc2[2*q+1]);
            }
        }
        #pragma unroll
        for (int q4 = 0; q4 < 8; q4++) {
            uint4 hv, lv;
            split2(acc2[4*q4+0], hv.x, lv.x);
            split2(acc2[4*q4+1], hv.y, lv.y);
            split2(acc2[4*q4+2], hv.z, lv.z);
            split2(acc2[4*q4+3], hv.w, lv.w);
            *(uint4*)(sm + OAH + t * 144 + q4 * 16) = hv;
            *(uint4*)(sm + OAL + t * 144 + q4 * 16) = lv;
        }
    }
    __syncthreads();

    // ---- Step B ----
    float acc[2][8][4];
    {
        const int cb = (lane & 3) * 2;
        #pragma unroll
        for (int nt = 0; nt < 8; nt++) {
            float2 bv = *(float2*)&bfs[nt * 8 + cb];
            #pragma unroll
            for (int m = 0; m < 2; m++) {
                acc[m][nt][0] = bv.x; acc[m][nt][1] = bv.y;
                acc[m][nt][2] = bv.x; acc[m][nt][3] = bv.y;
            }
        }
    }

    const int t0 = wid * 32;
    const int arow = ((lane >> 3) & 1) * 8 + (lane & 7);
    const int acol = (lane >> 4) * 16;

    #pragma unroll
    for (int ks = 0; ks < 4; ks++) {
        const int k0 = ks * 16;
        uint32_t Ah[2][4], Al[2][4];
        #pragma unroll
        for (int mt = 0; mt < 2; mt++) {
            uint32_t ad = sb + OAH + (uint32_t)(t0 + mt * 16 + arow) * 144 + (uint32_t)(k0 * 2 + acol);
            ldm4(Ah[mt][0], Ah[mt][1], Ah[mt][2], Ah[mt][3], ad);
            ldm4(Al[mt][0], Al[mt][1], Al[mt][2], Al[mt][3], ad + (OAL - OAH));
        }
        #pragma unroll
        for (int nt = 0; nt < 8; nt++) {
            const uint32_t boff = (uint32_t)((nt * 8 + (lane >> 2)) * 144 + k0 * 2 + (lane & 3) * 4);
            uint32_t bh0 = *(const uint32_t*)(sm + OWH + boff);
            uint32_t bh1 = *(const uint32_t*)(sm + OWH + boff + 16);
            uint32_t bl0 = *(const uint32_t*)(sm + OWL + boff);
            uint32_t bl1 = *(const uint32_t*)(sm + OWL + boff + 16);
            #pragma unroll
            for (int mt = 0; mt < 2; mt++) {
                mma16816(acc[mt][nt][0], acc[mt][nt][1], acc[mt][nt][2], acc[mt][nt][3],
                         Ah[mt][0], Ah[mt][1], Ah[mt][2], Ah[mt][3], bh0, bh1);
                mma16816(acc[mt][nt][0], acc[mt][nt][1], acc[mt][nt][2], acc[mt][nt][3],
                         Ah[mt][0], Ah[mt][1], Ah[mt][2], Ah[mt][3], bl0, bl1);
                mma16816(acc[mt][nt][0], acc[mt][nt][1], acc[mt][nt][2], acc[mt][nt][3],
                         Al[mt][0], Al[mt][1], Al[mt][2], Al[mt][3], bh0, bh1);
            }
        }
    }

    // ---- Direct fragment stores ----
    {
        float* Gb = g_G + (size_t)b * (G4_ * T_);
        const int cb = (lane & 3) * 2;
        #pragma unroll
        for (int mt = 0; mt < 2; mt++) {
            const int t = t0 + mt * 16 + (lane >> 2);
            #pragma unroll
            for (int nt = 0; nt < 8; nt++) {
                const int c = nt * 8 + cb;
                *(float2*)&Gb[(size_t)t * 64 + c]       = make_float2(acc[mt][nt][0], acc[mt][nt][1]);
                *(float2*)&Gb[(size_t)(t + 8) * 64 + c] = make_float2(acc[mt][nt][2], acc[mt][nt][3]);
            }
        }
    }
}

// ---------------- Phase 2: scan (R9-exact) ----------------
__global__ void __launch_bounds__(128) k_scan(const float* __restrict__ Wf)
{
    __shared__ float sg[4][2][8 * SGROW];

    const int tid = threadIdx.x, w = tid >> 5, l = tid & 31;
    const int b = blockIdx.x * 4 + w;
    const int j = l & 15;
    const int cA = (l < 16) ? l : (32 + j);
    const int cB = cA + 16;
    const int offA = cA + ((cA >> 5) << 4);
    const int offB = cB + ((cB >> 5) << 4);

    u64 wp[16];
    #pragma unroll
    for (int k = 0; k < 16; k++)
        wp[k] = pack2(Wf[(E_ + k) * G4_ + cA], Wf[(E_ + k) * G4_ + cB]);

    const float* Gb = g_G + (size_t)b * (G4_ * T_);

    int soff[4];
    #pragma unroll
    for (int k = 0; k < 4; k++) {
        int f  = l + 32 * k;
        int ti = f >> 4;
        int c4 = f & 15;
        soff[k] = ti * SGROW + c4 * 4 + ((c4 >> 3) << 4);
    }

    float h = 0.f, c = 0.f;

    float bU, kV, aV, bV;
    if (l < 16) { bU = 0.f;  kV = 1.f;  aV = 1.f;  bV = 0.f;  }
    else        { bU = 0.5f; kV = 0.5f; aV = 0.5f; bV = 0.5f; }

    float4 r[4];
    {
        const float4* src = (const float4*)Gb;
        #pragma unroll
        for (int k = 0; k < 4; k++) r[k] = src[l + 32 * k];
        #pragma unroll
        for (int k = 0; k < 4; k++) *(float4*)&sg[w][0][soff[k]] = r[k];
    }
    __syncwarp();

    for (int tg = 0; tg < TGRP; ++tg) {
        const int buf = tg & 1;
        if (tg < TGRP - 1) {
            const float4* src = (const float4*)(Gb + (size_t)(tg + 1) * 512);
            #pragma unroll
            for (int k = 0; k < 4; k++) r[k] = src[l + 32 * k];
        }
        const float* sgb = &sg[w][buf][0];
        #pragma unroll
        for (int i = 0; i < 8; i++) {
            float ga = sgb[i * SGROW + offA];
            float gb = sgb[i * SGROW + offB];
            float h0  = __shfl_sync(0xffffffffu, h, 0);
            float h1  = __shfl_sync(0xffffffffu, h, 1);
            float h2  = __shfl_sync(0xffffffffu, h, 2);
            float h3  = __shfl_sync(0xffffffffu, h, 3);
            float h4  = __shfl_sync(0xffffffffu, h, 4);
            float h5  = __shfl_sync(0xffffffffu, h, 5);
            float h6  = __shfl_sync(0xffffffffu, h, 6);
            float h7  = __shfl_sync(0xffffffffu, h, 7);
            float h8  = __shfl_sync(0xffffffffu, h, 8);
            float h9  = __shfl_sync(0xffffffffu, h, 9);
            float h10 = __shfl_sync(0xffffffffu, h, 10);
            float h11 = __shfl_sync(0xffffffffu, h, 11);
            float h12 = __shfl_sync(0xffffffffu, h, 12);
            float h13 = __shfl_sync(0xffffffffu, h, 13);
            float h14 = __shfl_sync(0xffffffffu, h, 14);
            float h15 = __shfl_sync(0xffffffffu, h, 15);

            u64 a0p = pack2(ga, gb);
            a0p = fma2(pack2(h0, h0),   wp[0],  a0p);
            a0p = fma2(pack2(h1, h1),   wp[1],  a0p);
            a0p = fma2(pack2(h2, h2),   wp[2],  a0p);
            a0p = fma2(pack2(h3, h3),   wp[3],  a0p);
            u64 a1p = fma2(pack2(h4, h4),   wp[4],  0ULL);
            a1p = fma2(pack2(h5, h5),   wp[5],  a1p);
            a1p = fma2(pack2(h6, h6),   wp[6],  a1p);
            a1p = fma2(pack2(h7, h7),   wp[7],  a1p);
            u64 a2p = fma2(pack2(h8, h8),   wp[8],  0ULL);
            a2p = fma2(pack2(h9, h9),   wp[9],  a2p);
            a2p = fma2(pack2(h10, h10), wp[10], a2p);
            a2p = fma2(pack2(h11, h11), wp[11], a2p);
            u64 a3p = fma2(pack2(h12, h12), wp[12], 0ULL);
            a3p = fma2(pack2(h13, h13), wp[13], a3p);
            a3p = fma2(pack2(h14, h14), wp[14], a3p);
            a3p = fma2(pack2(h15, h15), wp[15], a3p);
            u64 acc = add2(add2(a0p, a1p), add2(a2p, a3p));
            float xA, xB; unpack2(acc, xA, xB);

            float u = fmaf(0.5f, tanha(fmaf(0.5f, xA, bU)), 0.5f);
            float v = fmaf(aV, tanha(kV * xB), bV);
            float sf = __shfl_down_sync(0xffffffffu, u, 16);
            float so = __shfl_down_sync(0xffffffffu, v, 16);
            if (l < 16) {
                c = fmaf(sf, c, u * v);
                h = so * tanha(c);
            }
        }
        if (tg < TGRP - 1) {
            #pragma unroll
            for (int k = 0; k < 4; k++) *(float4*)&sg[w][buf ^ 1][soff[k]] = r[k];
            __syncwarp();
        }
    }
    if (l < 16) g_hf[b * H_ + l] = h;
}

// ---------------- Tail: bwd single step + head MLP (R9-exact) ----------------
__global__ void __launch_bounds__(256) k_tail(
    const float* __restrict__ x, const float* __restrict__ W0,
    const float* __restrict__ b0, const float* __restrict__ Wb,
    const float* __restrict__ bb,
    const float* __restrict__ W1, const float* __restrict__ b1,
    const float* __restrict__ W2, const float* __restrict__ b2,
    const float* __restrict__ W3, const float* __restrict__ b3,
    float* __restrict__ out)
{
    __shared__ float W0s[D_ * E_];
    __shared__ float Wbs[E_ * G4_];
    __shared__ float b0s[64], bbs[64];
    __shared__ float W1s[32 * 64], W2s[64 * 16], W3s[32];
    __shared__ float b1s[64], b2s[16], b3s[2];
    __shared__ float xsh[8][20];
    __shared__ __align__(16) float2 hes[8][64];
    __shared__ float hbs[8][16];
    __shared__ float insh[8][32], ush[8][64], vsh[8][16];

    const int tid = threadIdx.x, w = tid >> 5, l = tid & 31;
    const int b = blockIdx.x * 8 + w;

    for (int i = tid; i < D_ * E_;  i += 256) W0s[i] = W0[i];
    for (int i = tid; i < E_ * G4_; i += 256) Wbs[i] = Wb[i];
    for (int i = tid; i < 32 * 64;  i += 256) W1s[i] = W1[i];
    for (int i = tid; i < 64 * 16;  i += 256) W2s[i] = W2[i];
    if (tid < 32) W3s[tid] = W3[tid];
    if (tid < 64) { b0s[tid] = b0[tid]; bbs[tid] = bb[tid]; b1s[tid] = b1[tid]; }
    if (tid < 16) b2s[tid] = b2[tid];
    if (tid < 2)  b3s[tid] = b3[tid];
    __syncthreads();

    if (l < 20) xsh[w][l] = x[((size_t)b * T_ + (T_ - 1)) * D_ + l];
    __syncwarp();

    float a0 = b0s[l], a1 = b0s[l + 32];
    #pragma unroll
    for (int d = 0; d < D_; d++) {
        float xv = xsh[w][d];
        a0 = fmaf(xv, W0s[d * E_ + l],      a0);
        a1 = fmaf(xv, W0s[d * E_ + l + 32], a1);
    }
    a0 = fmaxf(a0, 0.f); a1 = fmaxf(a1, 0.f);
    hes[w][l]      = make_float2(a0, a0);
    hes[w][l + 32] = make_float2(a1, a1);
    __syncwarp();

    const int j = l & 15;
    const int cA = (l < 16) ? l : (32 + j);
    const int cB = cA + 16;
    u64 acc = pack2(bbs[cA], bbs[cB]);
    #pragma unroll 8
    for (int k = 0; k < E_; k++) {
        u64 hd = *(const u64*)&hes[w][k];
        acc = fma2(hd, pack2(Wbs[k * G4_ + cA], Wbs[k * G4_ + cB]), acc);
    }
    float xA, xB; unpack2(acc, xA, xB);

    float bU, kV, aV, bV;
    if (l < 16) { bU = 0.f;  kV = 1.f;  aV = 1.f;  bV = 0.f;  }
    else        { bU = 0.5f; kV = 0.5f; aV = 0.5f; bV = 0.5f; }
    float u = fmaf(0.5f, tanha(fmaf(0.5f, xA, bU)), 0.5f);
    float v = fmaf(aV, tanha(kV * xB), bV);
    float so = __shfl_down_sync(0xffffffffu, v, 16);
    if (l < 16) {
        float cc = u * v;
        hbs[w][l] = so * tanha(cc);
    }
    __syncwarp();

    insh[w][l] = (l < 16) ? g_hf[b * H_ + l] : hbs[w][l - 16];
    __syncwarp();

    float u0 = b1s[l], u1 = b1s[l + 32];
    #pragma unroll 8
    for (int k = 0; k < 32; k++) {
        float t = insh[w][k];
        u0 = fmaf(t, W1s[k * 64 + l],      u0);
        u1 = fmaf(t, W1s[k * 64 + l + 32], u1);
    }
    ush[w][l]      = fmaxf(u0, 0.f);
    ush[w][l + 32] = fmaxf(u1, 0.f);
    __syncwarp();

    if (l < 16) {
        float a = b2s[l];
        #pragma unroll 8
        for (int k = 0; k < 64; k++) a = fmaf(ush[w][k], W2s[k * 16 + l], a);
        vsh[w][l] = fmaxf(a, 0.f);
    }
    __syncwarp();

    if (l < 2) {
        float a = b3s[l];
        #pragma unroll
        for (int k = 0; k < 16; k++) a = fmaf(vsh[w][k], W3s[k * 2 + l], a);
        out[b * 2 + l] = a;
    }
}

extern "C" void kernel_launch(void* const* d_in, const int* in_sizes, int n_in,
                              void* d_out, int out_size)
{
    (void)in_sizes; (void)n_in; (void)out_size;
    const float* x  = (const float*)d_in[0];
    const float* W0 = (const float*)d_in[1];
    const float* b0 = (const float*)d_in[2];
    const float* Wf = (const float*)d_in[3];
    const float* bf = (const float*)d_in[4];
    const float* Wb = (const float*)d_in[5];
    const float* bb = (const float*)d_in[6];
    const float* W1 = (const float*)d_in[7];
    const float* b1 = (const float*)d_in[8];
    const float* W2 = (const float*)d_in[9];
    const float* b2 = (const float*)d_in[10];
    const float* W3 = (const float*)d_in[11];
    const float* b3 = (const float*)d_in[12];
    float* out = (float*)d_out;

    cudaFuncSetAttribute(k_phase1, cudaFuncAttributeMaxDynamicSharedMemorySize, (int)SMEM1);

    k_prep  <<<16, 256>>>(Wf);
    k_phase1<<<B_,     256, SMEM1>>>(x, W0, b0, bf);
    k_scan  <<<B_ / 4, 128>>>(Wf);
    k_tail  <<<B_ / 8, 256>>>(x, W0, b0, Wb, bb, W1, b1, W2, b2, W3, b3, out);
}

// round 12
// speedup vs baseline: 1.7083x; 1.1793x over previous
#include <cuda_runtime.h>
#include <cuda_bf16.h>
#include <cstdint>

#define B_  4096
#define T_  256
#define D_  20
#define E_  64
#define H_  16
#define G4_ 64
#define TGRP 32
#define SGROW 80

// G layout: [b][t(256)][c(64)]
__device__ float g_G[(size_t)B_ * G4_ * T_];
__device__ float g_hf[B_ * H_];
// Prepacked WfT bf16 hi/lo tiles (64 rows x 144B)
__device__ __align__(16) unsigned char g_WfH[9216];
__device__ __align__(16) unsigned char g_WfL[9216];
// Prepacked W0T bf16 hi/lo tiles (64 rows x 80B, K=32 zero-padded)
__device__ __align__(16) unsigned char g_W0H[5120];
__device__ __align__(16) unsigned char g_W0L[5120];

typedef unsigned long long u64;

__device__ __forceinline__ float tanha(float x){ float y; asm("tanh.approx.f32 %0,%1;":"=f"(y):"f"(x)); return y; }
__device__ __forceinline__ u64 pack2(float a,float b){ u64 r; asm("mov.b64 %0,{%1,%2};":"=l"(r):"f"(a),"f"(b)); return r; }
__device__ __forceinline__ void unpack2(u64 v,float&a,float&b){ asm("mov.b64 {%0,%1},%2;":"=f"(a),"=f"(b):"l"(v)); }
__device__ __forceinline__ u64 fma2(u64 a,u64 b,u64 c){ u64 d; asm("fma.rn.f32x2 %0,%1,%2,%3;":"=l"(d):"l"(a),"l"(b),"l"(c)); return d; }
__device__ __forceinline__ u64 add2(u64 a,u64 b){ u64 d; asm("add.rn.f32x2 %0,%1,%2;":"=l"(d):"l"(a),"l"(b)); return d; }
__device__ __forceinline__ uint32_t smem_u32(const void* p){
    uint32_t a; asm("{ .reg .u64 t; cvta.to.shared.u64 t, %1; cvt.u32.u64 %0, t; }":"=r"(a):"l"(p)); return a;
}
__device__ __forceinline__ void mma16816(float& c0, float& c1, float& c2, float& c3,
                                         uint32_t a0, uint32_t a1, uint32_t a2, uint32_t a3,
                                         uint32_t b0, uint32_t b1){
    asm volatile("mma.sync.aligned.m16n8k16.row.col.f32.bf16.bf16.f32 "
        "{%0,%1,%2,%3}, {%4,%5,%6,%7}, {%8,%9}, {%0,%1,%2,%3};"
        : "+f"(c0),"+f"(c1),"+f"(c2),"+f"(c3)
        : "r"(a0),"r"(a1),"r"(a2),"r"(a3),"r"(b0),"r"(b1));
}
__device__ __forceinline__ void ldm4(uint32_t& r0, uint32_t& r1, uint32_t& r2, uint32_t& r3, uint32_t a){
    asm volatile("ldmatrix.sync.aligned.m8n8.x4.shared.b16 {%0,%1,%2,%3}, [%4];"
        : "=r"(r0),"=r"(r1),"=r"(r2),"=r"(r3) : "r"(a));
}
// relu + bf16 hi/lo split
__device__ __forceinline__ void split2(u64 p, uint32_t& hi, uint32_t& lo){
    float v0, v1; unpack2(p, v0, v1);
    v0 = fmaxf(v0, 0.f); v1 = fmaxf(v1, 0.f);
    __nv_bfloat16 h0 = __float2bfloat16(v0), h1 = __float2bfloat16(v1);
    __nv_bfloat16 l0 = __float2bfloat16(v0 - __bfloat162float(h0));
    __nv_bfloat16 l1 = __float2bfloat16(v1 - __bfloat162float(h1));
    hi = (uint32_t)__bfloat16_as_ushort(h0) | ((uint32_t)__bfloat16_as_ushort(h1) << 16);
    lo = (uint32_t)__bfloat16_as_ushort(l0) | ((uint32_t)__bfloat16_as_ushort(l1) << 16);
}
// no-relu split (for x input)
__device__ __forceinline__ void split2nr(float v0, float v1, uint32_t& hi, uint32_t& lo){
    __nv_bfloat16 h0 = __float2bfloat16(v0), h1 = __float2bfloat16(v1);
    __nv_bfloat16 l0 = __float2bfloat16(v0 - __bfloat162float(h0));
    __nv_bfloat16 l1 = __float2bfloat16(v1 - __bfloat162float(h1));
    hi = (uint32_t)__bfloat16_as_ushort(h0) | ((uint32_t)__bfloat16_as_ushort(h1) << 16);
    lo = (uint32_t)__bfloat16_as_ushort(l0) | ((uint32_t)__bfloat16_as_ushort(l1) << 16);
}

// SMEM byte offsets (phase1)
#define OAH   0u          // x tiles -> hE tiles (256 x 144B)
#define OAL   36864u
#define OWH   73728u      // WfT (64 x 144B)
#define OWL   82944u
#define OW0H  92160u      // W0T (64 x 80B)
#define OW0L  97280u
#define OB0   102400u
#define OBF   102656u
#define SMEM1 102912u

// ---------------- Prepack: WfT (144B rows) + W0T (80B rows, K=32 padded) ----------------
__global__ void k_prep(const float* __restrict__ Wf, const float* __restrict__ W0)
{
    int i = blockIdx.x * 256 + threadIdx.x;
    if (i < 4096) {                                    // WfT
        int k = i >> 6, c = i & 63;
        float v = Wf[i];
        __nv_bfloat16 h = __float2bfloat16(v);
        __nv_bfloat16 l = __float2bfloat16(v - __bfloat162float(h));
        *(unsigned short*)(g_WfH + c * 144 + k * 2) = __bfloat16_as_ushort(h);
        *(unsigned short*)(g_WfL + c * 144 + k * 2) = __bfloat16_as_ushort(l);
        if (i < 64) {
            *(uint4*)(g_WfH + i * 144 + 128) = make_uint4(0,0,0,0);
            *(uint4*)(g_WfL + i * 144 + 128) = make_uint4(0,0,0,0);
        }
    }
    int j = i - 4096;                                  // W0T: 64 c x 32 k
    if (j >= 0 && j < 2048) {
        int k = j >> 6, c = j & 63;
        float v = (k < D_) ? W0[k * 64 + c] : 0.f;
        __nv_bfloat16 h = __float2bfloat16(v);
        __nv_bfloat16 l = __float2bfloat16(v - __bfloat162float(h));
        *(unsigned short*)(g_W0H + c * 80 + k * 2) = __bfloat16_as_ushort(h);
        *(unsigned short*)(g_W0L + c * 80 + k * 2) = __bfloat16_as_ushort(l);
        if (j < 64) {   // zero row padding bytes [64,80)
            *(uint4*)(g_W0H + j * 80 + 64) = make_uint4(0,0,0,0);
            *(uint4*)(g_W0L + j * 80 + 64) = make_uint4(0,0,0,0);
        }
    }
}

// ---------------- Phase 1: both GEMMs via 3-term bf16 HMMA ----------------
__global__ void __launch_bounds__(256, 2) k_phase1(
    const float* __restrict__ x, const float* __restrict__ b0,
    const float* __restrict__ bf)
{
    extern __shared__ char sm[];
    const uint32_t sb = smem_u32(sm);
    float* b0s = (float*)(sm + OB0);
    float* bfs = (float*)(sm + OBF);

    const int tid = threadIdx.x, wid = tid >> 5, lane = tid & 31;
    const int b = blockIdx.x;

    if (tid < 64) { b0s[tid] = b0[tid]; bfs[tid] = bf[tid]; }
    // copy prepacked weight tiles (linear, conflict-free)
    {
        const uint4* srcH = (const uint4*)g_WfH;
        const uint4* srcL = (const uint4*)g_WfL;
        #pragma unroll
        for (int q = 0; q < 3; q++) {
            int i = tid + q * 256;
            if (i < 576) {
                *(uint4*)(sm + OWH + i * 16) = srcH[i];
                *(uint4*)(sm + OWL + i * 16) = srcL[i];
            }
        }
        const uint4* s0H = (const uint4*)g_W0H;
        const uint4* s0L = (const uint4*)g_W0L;
        #pragma unroll
        for (int q = 0; q < 2; q++) {
            int i = tid + q * 256;
            if (i < 320) {
                *(uint4*)(sm + OW0H + i * 16) = s0H[i];
                *(uint4*)(sm + OW0L + i * 16) = s0L[i];
            }
        }
    }

    // ---- Stage x as bf16 hi/lo tiles (row t, 144B stride, k cols 0..31, pad zero) ----
    {
        const int t = tid;
        const float4* xp4 = (const float4*)(x + (size_t)b * (T_ * D_) + t * D_);
        float xv[20];
        #pragma unroll
        for (int q = 0; q < 5; q++) {
            float4 f = __ldg(xp4 + q);
            xv[4*q] = f.x; xv[4*q+1] = f.y; xv[4*q+2] = f.z; xv[4*q+3] = f.w;
        }
        uint32_t hw[16], lw[16];
        #pragma unroll
        for (int p = 0; p < 10; p++) split2nr(xv[2*p], xv[2*p+1], hw[p], lw[p]);
        #pragma unroll
        for (int p = 10; p < 16; p++) { hw[p] = 0u; lw[p] = 0u; }
        #pragma unroll
        for (int q = 0; q < 4; q++) {
            *(uint4*)(sm + OAH + t * 144 + q * 16) = make_uint4(hw[4*q], hw[4*q+1], hw[4*q+2], hw[4*q+3]);
            *(uint4*)(sm + OAL + t * 144 + q * 16) = make_uint4(lw[4*q], lw[4*q+1], lw[4*q+2], lw[4*q+3]);
        }
    }
    __syncthreads();

    const int t0 = wid * 32;
    const int arow = ((lane >> 3) & 1) * 8 + (lane & 7);
    const int acol = (lane >> 4) * 16;
    const int cb = (lane & 3) * 2;

    // ---- GEMM1: hE = relu(x @ W0 + b0), K=32 (2 k-steps), 3-term split ----
    float acc1[2][8][4];
    #pragma unroll
    for (int nt = 0; nt < 8; nt++) {
        float2 bv = *(float2*)&b0s[nt * 8 + cb];
        #pragma unroll
        for (int m = 0; m < 2; m++) {
            acc1[m][nt][0] = bv.x; acc1[m][nt][1] = bv.y;
            acc1[m][nt][2] = bv.x; acc1[m][nt][3] = bv.y;
        }
    }
    #pragma unroll
    for (int ks = 0; ks < 2; ks++) {
        const int k0 = ks * 16;
        uint32_t Ah[2][4], Al[2][4];
        #pragma unroll
        for (int mt = 0; mt < 2; mt++) {
            uint32_t ad = sb + OAH + (uint32_t)(t0 + mt * 16 + arow) * 144 + (uint32_t)(k0 * 2 + acol);
            ldm4(Ah[mt][0], Ah[mt][1], Ah[mt][2], Ah[mt][3], ad);
            ldm4(Al[mt][0], Al[mt][1], Al[mt][2], Al[mt][3], ad + (OAL - OAH));
        }
        #pragma unroll
        for (int nt = 0; nt < 8; nt++) {
            const uint32_t boff = (uint32_t)((nt * 8 + (lane >> 2)) * 80 + k0 * 2 + (lane & 3) * 4);
            uint32_t bh0 = *(const uint32_t*)(sm + OW0H + boff);
            uint32_t bh1 = *(const uint32_t*)(sm + OW0H + boff + 16);
            uint32_t bl0 = *(const uint32_t*)(sm + OW0L + boff);
            uint32_t bl1 = *(const uint32_t*)(sm + OW0L + boff + 16);
            #pragma unroll
            for (int mt = 0; mt < 2; mt++) {
                mma16816(acc1[mt][nt][0], acc1[mt][nt][1], acc1[mt][nt][2], acc1[mt][nt][3],
                         Ah[mt][0], Ah[mt][1], Ah[mt][2], Ah[mt][3], bh0, bh1);
                mma16816(acc1[mt][nt][0], acc1[mt][nt][1], acc1[mt][nt][2], acc1[mt][nt][3],
                         Ah[mt][0], Ah[mt][1], Ah[mt][2], Ah[mt][3], bl0, bl1);
                mma16816(acc1[mt][nt][0], acc1[mt][nt][1], acc1[mt][nt][2], acc1[mt][nt][3],
                         Al[mt][0], Al[mt][1], Al[mt][2], Al[mt][3], bh0, bh1);
            }
        }
    }
    __syncthreads();   // all x-tile reads done; overwrite region with hE

    // relu + split -> hE tiles (same region, same row stride)
    #pragma unroll
    for (int mt = 0; mt < 2; mt++) {
        const int r0 = t0 + mt * 16 + (lane >> 2);
        #pragma unroll
        for (int nt = 0; nt < 8; nt++) {
            const int c = nt * 8 + cb;
            uint32_t h0, l0, h1, l1;
            split2(pack2(acc1[mt][nt][0], acc1[mt][nt][1]), h0, l0);
            split2(pack2(acc1[mt][nt][2], acc1[mt][nt][3]), h1, l1);
            *(uint32_t*)(sm + OAH + r0 * 144 + c * 2)       = h0;
            *(uint32_t*)(sm + OAL + r0 * 144 + c * 2)       = l0;
            *(uint32_t*)(sm + OAH + (r0 + 8) * 144 + c * 2) = h1;
            *(uint32_t*)(sm + OAL + (r0 + 8) * 144 + c * 2) = l1;
        }
    }
    __syncthreads();

    // ---- GEMM2: G = hE @ WfT + bf (K=64, 4 k-steps, 3-term split) ----
    float acc[2][8][4];
    #pragma unroll
    for (int nt = 0; nt < 8; nt++) {
        float2 bv = *(float2*)&bfs[nt * 8 + cb];
        #pragma unroll
        for (int m = 0; m < 2; m++) {
            acc[m][nt][0] = bv.x; acc[m][nt][1] = bv.y;
            acc[m][nt][2] = bv.x; acc[m][nt][3] = bv.y;
        }
    }
    #pragma unroll
    for (int ks = 0; ks < 4; ks++) {
        const int k0 = ks * 16;
        uint32_t Ah[2][4], Al[2][4];
        #pragma unroll
        for (int mt = 0; mt < 2; mt++) {
            uint32_t ad = sb + OAH + (uint32_t)(t0 + mt * 16 + arow) * 144 + (uint32_t)(k0 * 2 + acol);
            ldm4(Ah[mt][0], Ah[mt][1], Ah[mt][2], Ah[mt][3], ad);
            ldm4(Al[mt][0], Al[mt][1], Al[mt][2], Al[mt][3], ad + (OAL - OAH));
        }
        #pragma unroll
        for (int nt = 0; nt < 8; nt++) {
            const uint32_t boff = (uint32_t)((nt * 8 + (lane >> 2)) * 144 + k0 * 2 + (lane & 3) * 4);
            uint32_t bh0 = *(const uint32_t*)(sm + OWH + boff);
            uint32_t bh1 = *(const uint32_t*)(sm + OWH + boff + 16);
            uint32_t bl0 = *(const uint32_t*)(sm + OWL + boff);
            uint32_t bl1 = *(const uint32_t*)(sm + OWL + boff + 16);
            #pragma unroll
            for (int mt = 0; mt < 2; mt++) {
                mma16816(acc[mt][nt][0], acc[mt][nt][1], acc[mt][nt][2], acc[mt][nt][3],
                         Ah[mt][0], Ah[mt][1], Ah[mt][2], Ah[mt][3], bh0, bh1);
                mma16816(acc[mt][nt][0], acc[mt][nt][1], acc[mt][nt][2], acc[mt][nt][3],
                         Ah[mt][0], Ah[mt][1], Ah[mt][2], Ah[mt][3], bl0, bl1);
                mma16816(acc[mt][nt][0], acc[mt][nt][1], acc[mt][nt][2], acc[mt][nt][3],
                         Al[mt][0], Al[mt][1], Al[mt][2], Al[mt][3], bh0, bh1);
            }
        }
    }

    // ---- Direct fragment stores ----
    {
        float* Gb = g_G + (size_t)b * (G4_ * T_);
        #pragma unroll
        for (int mt = 0; mt < 2; mt++) {
            const int t = t0 + mt * 16 + (lane >> 2);
            #pragma unroll
            for (int nt = 0; nt < 8; nt++) {
                const int c = nt * 8 + cb;
                *(float2*)&Gb[(size_t)t * 64 + c]       = make_float2(acc[mt][nt][0], acc[mt][nt][1]);
                *(float2*)&Gb[(size_t)(t + 8) * 64 + c] = make_float2(acc[mt][nt][2], acc[mt][nt][3]);
            }
        }
    }
}

// ---------------- Phase 2: scan (R11-exact) ----------------
__global__ void __launch_bounds__(128) k_scan(const float* __restrict__ Wf)
{
    __shared__ float sg[4][2][8 * SGROW];

    const int tid = threadIdx.x, w = tid >> 5, l = tid & 31;
    const int b = blockIdx.x * 4 + w;
    const int j = l & 15;
    const int cA = (l < 16) ? l : (32 + j);
    const int cB = cA + 16;
    const int offA = cA + ((cA >> 5) << 4);
    const int offB = cB + ((cB >> 5) << 4);

    u64 wp[16];
    #pragma unroll
    for (int k = 0; k < 16; k++)
        wp[k] = pack2(Wf[(E_ + k) * G4_ + cA], Wf[(E_ + k) * G4_ + cB]);

    const float* Gb = g_G + (size_t)b * (G4_ * T_);

    int soff[4];
    #pragma unroll
    for (int k = 0; k < 4; k++) {
        int f  = l + 32 * k;
        int ti = f >> 4;
        int c4 = f & 15;
        soff[k] = ti * SGROW + c4 * 4 + ((c4 >> 3) << 4);
    }

    float h = 0.f, c = 0.f;

    float bU, kV, aV, bV;
    if (l < 16) { bU = 0.f;  kV = 1.f;  aV = 1.f;  bV = 0.f;  }
    else        { bU = 0.5f; kV = 0.5f; aV = 0.5f; bV = 0.5f; }

    float4 r[4];
    {
        const float4* src = (const float4*)Gb;
        #pragma unroll
        for (int k = 0; k < 4; k++) r[k] = src[l + 32 * k];
        #pragma unroll
        for (int k = 0; k < 4; k++) *(float4*)&sg[w][0][soff[k]] = r[k];
    }
    __syncwarp();

    for (int tg = 0; tg < TGRP; ++tg) {
        const int buf = tg & 1;
        if (tg < TGRP - 1) {
            const float4* src = (const float4*)(Gb + (size_t)(tg + 1) * 512);
            #pragma unroll
            for (int k = 0; k < 4; k++) r[k] = src[l + 32 * k];
        }
        const float* sgb = &sg[w][buf][0];
        #pragma unroll
        for (int i = 0; i < 8; i++) {
            float ga = sgb[i * SGROW + offA];
            float gb = sgb[i * SGROW + offB];
            float h0  = __shfl_sync(0xffffffffu, h, 0);
            float h1  = __shfl_sync(0xffffffffu, h, 1);
            float h2  = __shfl_sync(0xffffffffu, h, 2);
            float h3  = __shfl_sync(0xffffffffu, h, 3);
            float h4  = __shfl_sync(0xffffffffu, h, 4);
            float h5  = __shfl_sync(0xffffffffu, h, 5);
            float h6  = __shfl_sync(0xffffffffu, h, 6);
            float h7  = __shfl_sync(0xffffffffu, h, 7);
            float h8  = __shfl_sync(0xffffffffu, h, 8);
            float h9  = __shfl_sync(0xffffffffu, h, 9);
            float h10 = __shfl_sync(0xffffffffu, h, 10);
            float h11 = __shfl_sync(0xffffffffu, h, 11);
            float h12 = __shfl_sync(0xffffffffu, h, 12);
            float h13 = __shfl_sync(0xffffffffu, h, 13);
            float h14 = __shfl_sync(0xffffffffu, h, 14);
            float h15 = __shfl_sync(0xffffffffu, h, 15);

            u64 a0p = pack2(ga, gb);
            a0p = fma2(pack2(h0, h0),   wp[0],  a0p);
            a0p = fma2(pack2(h1, h1),   wp[1],  a0p);
            a0p = fma2(pack2(h2, h2),   wp[2],  a0p);
            a0p = fma2(pack2(h3, h3),   wp[3],  a0p);
            u64 a1p = fma2(pack2(h4, h4),   wp[4],  0ULL);
            a1p = fma2(pack2(h5, h5),   wp[5],  a1p);
            a1p = fma2(pack2(h6, h6),   wp[6],  a1p);
            a1p = fma2(pack2(h7, h7),   wp[7],  a1p);
            u64 a2p = fma2(pack2(h8, h8),   wp[8],  0ULL);
            a2p = fma2(pack2(h9, h9),   wp[9],  a2p);
            a2p = fma2(pack2(h10, h10), wp[10], a2p);
            a2p = fma2(pack2(h11, h11), wp[11], a2p);
            u64 a3p = fma2(pack2(h12, h12), wp[12], 0ULL);
            a3p = fma2(pack2(h13, h13), wp[13], a3p);
            a3p = fma2(pack2(h14, h14), wp[14], a3p);
            a3p = fma2(pack2(h15, h15), wp[15], a3p);
            u64 acc = add2(add2(a0p, a1p), add2(a2p, a3p));
            float xA, xB; unpack2(acc, xA, xB);

            float u = fmaf(0.5f, tanha(fmaf(0.5f, xA, bU)), 0.5f);
            float v = fmaf(aV, tanha(kV * xB), bV);
            float sf = __shfl_down_sync(0xffffffffu, u, 16);
            float so = __shfl_down_sync(0xffffffffu, v, 16);
            if (l < 16) {
                c = fmaf(sf, c, u * v);
                h = so * tanha(c);
            }
        }
        if (tg < TGRP - 1) {
            #pragma unroll
            for (int k = 0; k < 4; k++) *(float4*)&sg[w][buf ^ 1][soff[k]] = r[k];
            __syncwarp();
        }
    }
    if (l < 16) g_hf[b * H_ + l] = h;
}

// ---------------- Tail: bwd single step + head MLP (R11-exact) ----------------
__global__ void __launch_bounds__(256) k_tail(
    const float* __restrict__ x, const float* __restrict__ W0,
    const float* __restrict__ b0, const float* __restrict__ Wb,
    const float* __restrict__ bb,
    const float* __restrict__ W1, const float* __restrict__ b1,
    const float* __restrict__ W2, const float* __restrict__ b2,
    const float* __restrict__ W3, const float* __restrict__ b3,
    float* __restrict__ out)
{
    __shared__ float W0s[D_ * E_];
    __shared__ float Wbs[E_ * G4_];
    __shared__ float b0s[64], bbs[64];
    __shared__ float W1s[32 * 64], W2s[64 * 16], W3s[32];
    __shared__ float b1s[64], b2s[16], b3s[2];
    __shared__ float xsh[8][20];
    __shared__ __align__(16) float2 hes[8][64];
    __shared__ float hbs[8][16];
    __shared__ float insh[8][32], ush[8][64], vsh[8][16];

    const int tid = threadIdx.x, w = tid >> 5, l = tid & 31;
    const int b = blockIdx.x * 8 + w;

    for (int i = tid; i < D_ * E_;  i += 256) W0s[i] = W0[i];
    for (int i = tid; i < E_ * G4_; i += 256) Wbs[i] = Wb[i];
    for (int i = tid; i < 32 * 64;  i += 256) W1s[i] = W1[i];
    for (int i = tid; i < 64 * 16;  i += 256) W2s[i] = W2[i];
    if (tid < 32) W3s[tid] = W3[tid];
    if (tid < 64) { b0s[tid] = b0[tid]; bbs[tid] = bb[tid]; b1s[tid] = b1[tid]; }
    if (tid < 16) b2s[tid] = b2[tid];
    if (tid < 2)  b3s[tid] = b3[tid];
    __syncthreads();

    if (l < 20) xsh[w][l] = x[((size_t)b * T_ + (T_ - 1)) * D_ + l];
    __syncwarp();

    float a0 = b0s[l], a1 = b0s[l + 32];
    #pragma unroll
    for (int d = 0; d < D_; d++) {
        float xv = xsh[w][d];
        a0 = fmaf(xv, W0s[d * E_ + l],      a0);
        a1 = fmaf(xv, W0s[d * E_ + l + 32], a1);
    }
    a0 = fmaxf(a0, 0.f); a1 = fmaxf(a1, 0.f);
    hes[w][l]      = make_float2(a0, a0);
    hes[w][l + 32] = make_float2(a1, a1);
    __syncwarp();

    const int j = l & 15;
    const int cA = (l < 16) ? l : (32 + j);
    const int cB = cA + 16;
    u64 acc = pack2(bbs[cA], bbs[cB]);
    #pragma unroll 8
    for (int k = 0; k < E_; k++) {
        u64 hd = *(const u64*)&hes[w][k];
        acc = fma2(hd, pack2(Wbs[k * G4_ + cA], Wbs[k * G4_ + cB]), acc);
    }
    float xA, xB; unpack2(acc, xA, xB);

    float bU, kV, aV, bV;
    if (l < 16) { bU = 0.f;  kV = 1.f;  aV = 1.f;  bV = 0.f;  }
    else        { bU = 0.5f; kV = 0.5f; aV = 0.5f; bV = 0.5f; }
    float u = fmaf(0.5f, tanha(fmaf(0.5f, xA, bU)), 0.5f);
    float v = fmaf(aV, tanha(kV * xB), bV);
    float so = __shfl_down_sync(0xffffffffu, v, 16);
    if (l < 16) {
        float cc = u * v;
        hbs[w][l] = so * tanha(cc);
    }
    __syncwarp();

    insh[w][l] = (l < 16) ? g_hf[b * H_ + l] : hbs[w][l - 16];
    __syncwarp();

    float u0 = b1s[l], u1 = b1s[l + 32];
    #pragma unroll 8
    for (int k = 0; k < 32; k++) {
        float t = insh[w][k];
        u0 = fmaf(t, W1s[k * 64 + l],      u0);
        u1 = fmaf(t, W1s[k * 64 + l + 32], u1);
    }
    ush[w][l]      = fmaxf(u0, 0.f);
    ush[w][l + 32] = fmaxf(u1, 0.f);
    __syncwarp();

    if (l < 16) {
        float a = b2s[l];
        #pragma unroll 8
        for (int k = 0; k < 64; k++) a = fmaf(ush[w][k], W2s[k * 16 + l], a);
        vsh[w][l] = fmaxf(a, 0.f);
    }
    __syncwarp();

    if (l < 2) {
        float a = b3s[l];
        #pragma unroll
        for (int k = 0; k < 16; k++) a = fmaf(vsh[w][k], W3s[k * 2 + l], a);
        out[b * 2 + l] = a;
    }
}

extern "C" void kernel_launch(void* const* d_in, const int* in_sizes, int n_in,
                              void* d_out, int out_size)
{
    (void)in_sizes; (void)n_in; (void)out_size;
    const float* x  = (const float*)d_in[0];
    const float* W0 = (const float*)d_in[1];
    const float* b0 = (const float*)d_in[2];
    const float* Wf = (const float*)d_in[3];
    const float* bf = (const float*)d_in[4];
    const float* Wb = (const float*)d_in[5];
    const float* bb = (const float*)d_in[6];
    const float* W1 = (const float*)d_in[7];
    const float* b1 = (const float*)d_in[8];
    const float* W2 = (const float*)d_in[9];
    const float* b2 = (const float*)d_in[10];
    const float* W3 = (const float*)d_in[11];
    const float* b3 = (const float*)d_in[12];
    float* out = (float*)d_out;

    cudaFuncSetAttribute(k_phase1, cudaFuncAttributeMaxDynamicSharedMemorySize, (int)SMEM1);

    k_prep  <<<24, 256>>>(Wf, W0);
    k_phase1<<<B_,     256, SMEM1>>>(x, b0, bf);
    k_scan  <<<B_ / 4, 128>>>(Wf);
    k_tail  <<<B_ / 8, 256>>>(x, W0, b0, Wb, bb, W1, b1, W2, b2, W3, b3, out);
}

// round 13
// speedup vs baseline: 1.8228x; 1.0670x over previous
#include <cuda_runtime.h>
#include <cuda_bf16.h>
#include <cuda_fp16.h>
#include <cstdint>

#define B_  4096
#define T_  256
#define D_  20
#define E_  64
#define H_  16
#define G4_ 64
#define TGRP 32
#define SGROW 80

// G layout: [b][t(256)][c(64)]  fp16
__device__ __half g_G[(size_t)B_ * G4_ * T_];
__device__ float g_hf[B_ * H_];
__device__ __align__(16) unsigned char g_WfH[9216];
__device__ __align__(16) unsigned char g_WfL[9216];
__device__ __align__(16) unsigned char g_W0H[5120];
__device__ __align__(16) unsigned char g_W0L[5120];

typedef unsigned long long u64;

__device__ __forceinline__ float tanha(float x){ float y; asm("tanh.approx.f32 %0,%1;":"=f"(y):"f"(x)); return y; }
__device__ __forceinline__ u64 pack2(float a,float b){ u64 r; asm("mov.b64 %0,{%1,%2};":"=l"(r):"f"(a),"f"(b)); return r; }
__device__ __forceinline__ void unpack2(u64 v,float&a,float&b){ asm("mov.b64 {%0,%1},%2;":"=f"(a),"=f"(b):"l"(v)); }
__device__ __forceinline__ u64 fma2(u64 a,u64 b,u64 c){ u64 d; asm("fma.rn.f32x2 %0,%1,%2,%3;":"=l"(d):"l"(a),"l"(b),"l"(c)); return d; }
__device__ __forceinline__ u64 add2(u64 a,u64 b){ u64 d; asm("add.rn.f32x2 %0,%1,%2;":"=l"(d):"l"(a),"l"(b)); return d; }
__device__ __forceinline__ uint32_t smem_u32(const void* p){
    uint32_t a; asm("{ .reg .u64 t; cvta.to.shared.u64 t, %1; cvt.u32.u64 %0, t; }":"=r"(a):"l"(p)); return a;
}
__device__ __forceinline__ void mma16816(float& c0, float& c1, float& c2, float& c3,
                                         uint32_t a0, uint32_t a1, uint32_t a2, uint32_t a3,
                                         uint32_t b0, uint32_t b1){
    asm volatile("mma.sync.aligned.m16n8k16.row.col.f32.bf16.bf16.f32 "
        "{%0,%1,%2,%3}, {%4,%5,%6,%7}, {%8,%9}, {%0,%1,%2,%3};"
        : "+f"(c0),"+f"(c1),"+f"(c2),"+f"(c3)
        : "r"(a0),"r"(a1),"r"(a2),"r"(a3),"r"(b0),"r"(b1));
}
__device__ __forceinline__ void ldm4(uint32_t& r0, uint32_t& r1, uint32_t& r2, uint32_t& r3, uint32_t a){
    asm volatile("ldmatrix.sync.aligned.m8n8.x4.shared.b16 {%0,%1,%2,%3}, [%4];"
        : "=r"(r0),"=r"(r1),"=r"(r2),"=r"(r3) : "r"(a));
}
__device__ __forceinline__ void split2(u64 p, uint32_t& hi, uint32_t& lo){
    float v0, v1; unpack2(p, v0, v1);
    v0 = fmaxf(v0, 0.f); v1 = fmaxf(v1, 0.f);
    __nv_bfloat16 h0 = __float2bfloat16(v0), h1 = __float2bfloat16(v1);
    __nv_bfloat16 l0 = __float2bfloat16(v0 - __bfloat162float(h0));
    __nv_bfloat16 l1 = __float2bfloat16(v1 - __bfloat162float(h1));
    hi = (uint32_t)__bfloat16_as_ushort(h0) | ((uint32_t)__bfloat16_as_ushort(h1) << 16);
    lo = (uint32_t)__bfloat16_as_ushort(l0) | ((uint32_t)__bfloat16_as_ushort(l1) << 16);
}
__device__ __forceinline__ void split2nr(float v0, float v1, uint32_t& hi, uint32_t& lo){
    __nv_bfloat16 h0 = __float2bfloat16(v0), h1 = __float2bfloat16(v1);
    __nv_bfloat16 l0 = __float2bfloat16(v0 - __bfloat162float(h0));
    __nv_bfloat16 l1 = __float2bfloat16(v1 - __bfloat162float(h1));
    hi = (uint32_t)__bfloat16_as_ushort(h0) | ((uint32_t)__bfloat16_as_ushort(h1) << 16);
    lo = (uint32_t)__bfloat16_as_ushort(l0) | ((uint32_t)__bfloat16_as_ushort(l1) << 16);
}

// SMEM byte offsets (phase1)
#define OAH   0u
#define OAL   36864u
#define OWH   73728u
#define OWL   82944u
#define OW0H  92160u
#define OW0L  97280u
#define OB0   102400u
#define OBF   102656u
#define SMEM1 102912u

// ---------------- Prepack (R12-exact) ----------------
__global__ void k_prep(const float* __restrict__ Wf, const float* __restrict__ W0)
{
    int i = blockIdx.x * 256 + threadIdx.x;
    if (i < 4096) {
        int k = i >> 6, c = i & 63;
        float v = Wf[i];
        __nv_bfloat16 h = __float2bfloat16(v);
        __nv_bfloat16 l = __float2bfloat16(v - __bfloat162float(h));
        *(unsigned short*)(g_WfH + c * 144 + k * 2) = __bfloat16_as_ushort(h);
        *(unsigned short*)(g_WfL + c * 144 + k * 2) = __bfloat16_as_ushort(l);
        if (i < 64) {
            *(uint4*)(g_WfH + i * 144 + 128) = make_uint4(0,0,0,0);
            *(uint4*)(g_WfL + i * 144 + 128) = make_uint4(0,0,0,0);
        }
    }
    int j = i - 4096;
    if (j >= 0 && j < 2048) {
        int k = j >> 6, c = j & 63;
        float v = (k < D_) ? W0[k * 64 + c] : 0.f;
        __nv_bfloat16 h = __float2bfloat16(v);
        __nv_bfloat16 l = __float2bfloat16(v - __bfloat162float(h));
        *(unsigned short*)(g_W0H + c * 80 + k * 2) = __bfloat16_as_ushort(h);
        *(unsigned short*)(g_W0L + c * 80 + k * 2) = __bfloat16_as_ushort(l);
        if (j < 64) {
            *(uint4*)(g_W0H + j * 80 + 64) = make_uint4(0,0,0,0);
            *(uint4*)(g_W0L + j * 80 + 64) = make_uint4(0,0,0,0);
        }
    }
}

// ---------------- Phase 1 (R12 body; G stored as fp16) ----------------
__global__ void __launch_bounds__(256, 2) k_phase1(
    const float* __restrict__ x, const float* __restrict__ b0,
    const float* __restrict__ bf)
{
    extern __shared__ char sm[];
    const uint32_t sb = smem_u32(sm);
    float* b0s = (float*)(sm + OB0);
    float* bfs = (float*)(sm + OBF);

    const int tid = threadIdx.x, wid = tid >> 5, lane = tid & 31;
    const int b = blockIdx.x;

    if (tid < 64) { b0s[tid] = b0[tid]; bfs[tid] = bf[tid]; }
    {
        const uint4* srcH = (const uint4*)g_WfH;
        const uint4* srcL = (const uint4*)g_WfL;
        #pragma unroll
        for (int q = 0; q < 3; q++) {
            int i = tid + q * 256;
            if (i < 576) {
                *(uint4*)(sm + OWH + i * 16) = srcH[i];
                *(uint4*)(sm + OWL + i * 16) = srcL[i];
            }
        }
        const uint4* s0H = (const uint4*)g_W0H;
        const uint4* s0L = (const uint4*)g_W0L;
        #pragma unroll
        for (int q = 0; q < 2; q++) {
            int i = tid + q * 256;
            if (i < 320) {
                *(uint4*)(sm + OW0H + i * 16) = s0H[i];
                *(uint4*)(sm + OW0L + i * 16) = s0L[i];
            }
        }
    }

    // Stage x as bf16 hi/lo tiles
    {
        const int t = tid;
        const float4* xp4 = (const float4*)(x + (size_t)b * (T_ * D_) + t * D_);
        float xv[20];
        #pragma unroll
        for (int q = 0; q < 5; q++) {
            float4 f = __ldg(xp4 + q);
            xv[4*q] = f.x; xv[4*q+1] = f.y; xv[4*q+2] = f.z; xv[4*q+3] = f.w;
        }
        uint32_t hw[16], lw[16];
        #pragma unroll
        for (int p = 0; p < 10; p++) split2nr(xv[2*p], xv[2*p+1], hw[p], lw[p]);
        #pragma unroll
        for (int p = 10; p < 16; p++) { hw[p] = 0u; lw[p] = 0u; }
        #pragma unroll
        for (int q = 0; q < 4; q++) {
            *(uint4*)(sm + OAH + t * 144 + q * 16) = make_uint4(hw[4*q], hw[4*q+1], hw[4*q+2], hw[4*q+3]);
            *(uint4*)(sm + OAL + t * 144 + q * 16) = make_uint4(lw[4*q], lw[4*q+1], lw[4*q+2], lw[4*q+3]);
        }
    }
    __syncthreads();

    const int t0 = wid * 32;
    const int arow = ((lane >> 3) & 1) * 8 + (lane & 7);
    const int acol = (lane >> 4) * 16;
    const int cb = (lane & 3) * 2;

    // GEMM1
    float acc1[2][8][4];
    #pragma unroll
    for (int nt = 0; nt < 8; nt++) {
        float2 bv = *(float2*)&b0s[nt * 8 + cb];
        #pragma unroll
        for (int m = 0; m < 2; m++) {
            acc1[m][nt][0] = bv.x; acc1[m][nt][1] = bv.y;
            acc1[m][nt][2] = bv.x; acc1[m][nt][3] = bv.y;
        }
    }
    #pragma unroll
    for (int ks = 0; ks < 2; ks++) {
        const int k0 = ks * 16;
        uint32_t Ah[2][4], Al[2][4];
        #pragma unroll
        for (int mt = 0; mt < 2; mt++) {
            uint32_t ad = sb + OAH + (uint32_t)(t0 + mt * 16 + arow) * 144 + (uint32_t)(k0 * 2 + acol);
            ldm4(Ah[mt][0], Ah[mt][1], Ah[mt][2], Ah[mt][3], ad);
            ldm4(Al[mt][0], Al[mt][1], Al[mt][2], Al[mt][3], ad + (OAL - OAH));
        }
        #pragma unroll
        for (int nt = 0; nt < 8; nt++) {
            const uint32_t boff = (uint32_t)((nt * 8 + (lane >> 2)) * 80 + k0 * 2 + (lane & 3) * 4);
            uint32_t bh0 = *(const uint32_t*)(sm + OW0H + boff);
            uint32_t bh1 = *(const uint32_t*)(sm + OW0H + boff + 16);
            uint32_t bl0 = *(const uint32_t*)(sm + OW0L + boff);
            uint32_t bl1 = *(const uint32_t*)(sm + OW0L + boff + 16);
            #pragma unroll
            for (int mt = 0; mt < 2; mt++) {
                mma16816(acc1[mt][nt][0], acc1[mt][nt][1], acc1[mt][nt][2], acc1[mt][nt][3],
                         Ah[mt][0], Ah[mt][1], Ah[mt][2], Ah[mt][3], bh0, bh1);
                mma16816(acc1[mt][nt][0], acc1[mt][nt][1], acc1[mt][nt][2], acc1[mt][nt][3],
                         Ah[mt][0], Ah[mt][1], Ah[mt][2], Ah[mt][3], bl0, bl1);
                mma16816(acc1[mt][nt][0], acc1[mt][nt][1], acc1[mt][nt][2], acc1[mt][nt][3],
                         Al[mt][0], Al[mt][1], Al[mt][2], Al[mt][3], bh0, bh1);
            }
        }
    }
    __syncthreads();

    // relu + split -> hE tiles
    #pragma unroll
    for (int mt = 0; mt < 2; mt++) {
        const int r0 = t0 + mt * 16 + (lane >> 2);
        #pragma unroll
        for (int nt = 0; nt < 8; nt++) {
            const int c = nt * 8 + cb;
            uint32_t h0, l0, h1, l1;
            split2(pack2(acc1[mt][nt][0], acc1[mt][nt][1]), h0, l0);
            split2(pack2(acc1[mt][nt][2], acc1[mt][nt][3]), h1, l1);
            *(uint32_t*)(sm + OAH + r0 * 144 + c * 2)       = h0;
            *(uint32_t*)(sm + OAL + r0 * 144 + c * 2)       = l0;
            *(uint32_t*)(sm + OAH + (r0 + 8) * 144 + c * 2) = h1;
            *(uint32_t*)(sm + OAL + (r0 + 8) * 144 + c * 2) = l1;
        }
    }
    __syncthreads();

    // GEMM2
    float acc[2][8][4];
    #pragma unroll
    for (int nt = 0; nt < 8; nt++) {
        float2 bv = *(float2*)&bfs[nt * 8 + cb];
        #pragma unroll
        for (int m = 0; m < 2; m++) {
            acc[m][nt][0] = bv.x; acc[m][nt][1] = bv.y;
            acc[m][nt][2] = bv.x; acc[m][nt][3] = bv.y;
        }
    }
    #pragma unroll
    for (int ks = 0; ks < 4; ks++) {
        const int k0 = ks * 16;
        uint32_t Ah[2][4], Al[2][4];
        #pragma unroll
        for (int mt = 0; mt < 2; mt++) {
            uint32_t ad = sb + OAH + (uint32_t)(t0 + mt * 16 + arow) * 144 + (uint32_t)(k0 * 2 + acol);
            ldm4(Ah[mt][0], Ah[mt][1], Ah[mt][2], Ah[mt][3], ad);
            ldm4(Al[mt][0], Al[mt][1], Al[mt][2], Al[mt][3], ad + (OAL - OAH));
        }
        #pragma unroll
        for (int nt = 0; nt < 8; nt++) {
            const uint32_t boff = (uint32_t)((nt * 8 + (lane >> 2)) * 144 + k0 * 2 + (lane & 3) * 4);
            uint32_t bh0 = *(const uint32_t*)(sm + OWH + boff);
            uint32_t bh1 = *(const uint32_t*)(sm + OWH + boff + 16);
            uint32_t bl0 = *(const uint32_t*)(sm + OWL + boff);
            uint32_t bl1 = *(const uint32_t*)(sm + OWL + boff + 16);
            #pragma unroll
            for (int mt = 0; mt < 2; mt++) {
                mma16816(acc[mt][nt][0], acc[mt][nt][1], acc[mt][nt][2], acc[mt][nt][3],
                         Ah[mt][0], Ah[mt][1], Ah[mt][2], Ah[mt][3], bh0, bh1);
                mma16816(acc[mt][nt][0], acc[mt][nt][1], acc[mt][nt][2], acc[mt][nt][3],
                         Ah[mt][0], Ah[mt][1], Ah[mt][2], Ah[mt][3], bl0, bl1);
                mma16816(acc[mt][nt][0], acc[mt][nt][1], acc[mt][nt][2], acc[mt][nt][3],
                         Al[mt][0], Al[mt][1], Al[mt][2], Al[mt][3], bh0, bh1);
            }
        }
    }

    // ---- fp16 fragment stores ----
    {
        __half* Gb = g_G + (size_t)b * (G4_ * T_);
        #pragma unroll
        for (int mt = 0; mt < 2; mt++) {
            const int t = t0 + mt * 16 + (lane >> 2);
            #pragma unroll
            for (int nt = 0; nt < 8; nt++) {
                const int c = nt * 8 + cb;
                *(__half2*)&Gb[(size_t)t * 64 + c]       = __floats2half2_rn(acc[mt][nt][0], acc[mt][nt][1]);
                *(__half2*)&Gb[(size_t)(t + 8) * 64 + c] = __floats2half2_rn(acc[mt][nt][2], acc[mt][nt][3]);
            }
        }
    }
}

// ---------------- Phase 2: scan (fp16 G loads; inner loop unchanged) ----------------
__global__ void __launch_bounds__(128) k_scan(const float* __restrict__ Wf)
{
    __shared__ float sg[4][2][8 * SGROW];

    const int tid = threadIdx.x, w = tid >> 5, l = tid & 31;
    const int b = blockIdx.x * 4 + w;
    const int j = l & 15;
    const int cA = (l < 16) ? l : (32 + j);
    const int cB = cA + 16;
    const int offA = cA + ((cA >> 5) << 4);
    const int offB = cB + ((cB >> 5) << 4);

    u64 wp[16];
    #pragma unroll
    for (int k = 0; k < 16; k++)
        wp[k] = pack2(Wf[(E_ + k) * G4_ + cA], Wf[(E_ + k) * G4_ + cB]);

    const __half* Gb = g_G + (size_t)b * (G4_ * T_);

    // staging offsets: lane handles uint4-of-halves f = l, l+32 (64 per group)
    // f -> t = f>>3, float4 col pair c4 = (f&7)*2, (f&7)*2+1
    int soff[2][2];
    #pragma unroll
    for (int k = 0; k < 2; k++) {
        int f  = l + 32 * k;
        int ti = f >> 3;
        int c4a = (f & 7) * 2;
        soff[k][0] = ti * SGROW + c4a * 4 + ((c4a >> 3) << 4);
        int c4b = c4a + 1;
        soff[k][1] = ti * SGROW + c4b * 4 + ((c4b >> 3) << 4);
    }

    float h = 0.f, c = 0.f;

    float bU, kV, aV, bV;
    if (l < 16) { bU = 0.f;  kV = 1.f;  aV = 1.f;  bV = 0.f;  }
    else        { bU = 0.5f; kV = 0.5f; aV = 0.5f; bV = 0.5f; }

    uint4 r[2];
    // stage group 0
    {
        const uint4* src = (const uint4*)Gb;        // 64 uint4 per group
        #pragma unroll
        for (int k = 0; k < 2; k++) r[k] = src[l + 32 * k];
        #pragma unroll
        for (int k = 0; k < 2; k++) {
            const __half2* hp2 = (const __half2*)&r[k];
            float2 f0 = __half22float2(hp2[0]);
            float2 f1 = __half22float2(hp2[1]);
            float2 f2 = __half22float2(hp2[2]);
            float2 f3 = __half22float2(hp2[3]);
            *(float4*)&sg[w][0][soff[k][0]] = make_float4(f0.x, f0.y, f1.x, f1.y);
            *(float4*)&sg[w][0][soff[k][1]] = make_float4(f2.x, f2.y, f3.x, f3.y);
        }
    }
    __syncwarp();

    for (int tg = 0; tg < TGRP; ++tg) {
        const int buf = tg & 1;
        if (tg < TGRP - 1) {
            const uint4* src = (const uint4*)(Gb + (size_t)(tg + 1) * 512);
            #pragma unroll
            for (int k = 0; k < 2; k++) r[k] = src[l + 32 * k];
        }
        const float* sgb = &sg[w][buf][0];
        #pragma unroll
        for (int i = 0; i < 8; i++) {
            float ga = sgb[i * SGROW + offA];
            float gb = sgb[i * SGROW + offB];
            float h0  = __shfl_sync(0xffffffffu, h, 0);
            float h1  = __shfl_sync(0xffffffffu, h, 1);
            float h2  = __shfl_sync(0xffffffffu, h, 2);
            float h3  = __shfl_sync(0xffffffffu, h, 3);
            float h4  = __shfl_sync(0xffffffffu, h, 4);
            float h5  = __shfl_sync(0xffffffffu, h, 5);
            float h6  = __shfl_sync(0xffffffffu, h, 6);
            float h7  = __shfl_sync(0xffffffffu, h, 7);
            float h8  = __shfl_sync(0xffffffffu, h, 8);
            float h9  = __shfl_sync(0xffffffffu, h, 9);
            float h10 = __shfl_sync(0xffffffffu, h, 10);
            float h11 = __shfl_sync(0xffffffffu, h, 11);
            float h12 = __shfl_sync(0xffffffffu, h, 12);
            float h13 = __shfl_sync(0xffffffffu, h, 13);
            float h14 = __shfl_sync(0xffffffffu, h, 14);
            float h15 = __shfl_sync(0xffffffffu, h, 15);

            u64 a0p = pack2(ga, gb);
            a0p = fma2(pack2(h0, h0),   wp[0],  a0p);
            a0p = fma2(pack2(h1, h1),   wp[1],  a0p);
            a0p = fma2(pack2(h2, h2),   wp[2],  a0p);
            a0p = fma2(pack2(h3, h3),   wp[3],  a0p);
            u64 a1p = fma2(pack2(h4, h4),   wp[4],  0ULL);
            a1p = fma2(pack2(h5, h5),   wp[5],  a1p);
            a1p = fma2(pack2(h6, h6),   wp[6],  a1p);
            a1p = fma2(pack2(h7, h7),   wp[7],  a1p);
            u64 a2p = fma2(pack2(h8, h8),   wp[8],  0ULL);
            a2p = fma2(pack2(h9, h9),   wp[9],  a2p);
            a2p = fma2(pack2(h10, h10), wp[10], a2p);
            a2p = fma2(pack2(h11, h11), wp[11], a2p);
            u64 a3p = fma2(pack2(h12, h12), wp[12], 0ULL);
            a3p = fma2(pack2(h13, h13), wp[13], a3p);
            a3p = fma2(pack2(h14, h14), wp[14], a3p);
            a3p = fma2(pack2(h15, h15), wp[15], a3p);
            u64 acc = add2(add2(a0p, a1p), add2(a2p, a3p));
            float xA, xB; unpack2(acc, xA, xB);

            float u = fmaf(0.5f, tanha(fmaf(0.5f, xA, bU)), 0.5f);
            float v = fmaf(aV, tanha(kV * xB), bV);
            float sf = __shfl_down_sync(0xffffffffu, u, 16);
            float so = __shfl_down_sync(0xffffffffu, v, 16);
            if (l < 16) {
                c = fmaf(sf, c, u * v);
                h = so * tanha(c);
            }
        }
        if (tg < TGRP - 1) {
            #pragma unroll
            for (int k = 0; k < 2; k++) {
                const __half2* hp2 = (const __half2*)&r[k];
                float2 f0 = __half22float2(hp2[0]);
                float2 f1 = __half22float2(hp2[1]);
                float2 f2 = __half22float2(hp2[2]);
                float2 f3 = __half22float2(hp2[3]);
                *(float4*)&sg[w][buf ^ 1][soff[k][0]] = make_float4(f0.x, f0.y, f1.x, f1.y);
                *(float4*)&sg[w][buf ^ 1][soff[k][1]] = make_float4(f2.x, f2.y, f3.x, f3.y);
            }
            __syncwarp();
        }
    }
    if (l < 16) g_hf[b * H_ + l] = h;
}

// ---------------- Tail (R12-exact) ----------------
__global__ void __launch_bounds__(256) k_tail(
    const float* __restrict__ x, const float* __restrict__ W0,
    const float* __restrict__ b0, const float* __restrict__ Wb,
    const float* __restrict__ bb,
    const float* __restrict__ W1, const float* __restrict__ b1,
    const float* __restrict__ W2, const float* __restrict__ b2,
    const float* __restrict__ W3, const float* __restrict__ b3,
    float* __restrict__ out)
{
    __shared__ float W0s[D_ * E_];
    __shared__ float Wbs[E_ * G4_];
    __shared__ float b0s[64], bbs[64];
    __shared__ float W1s[32 * 64], W2s[64 * 16], W3s[32];
    __shared__ float b1s[64], b2s[16], b3s[2];
    __shared__ float xsh[8][20];
    __shared__ __align__(16) float2 hes[8][64];
    __shared__ float hbs[8][16];
    __shared__ float insh[8][32], ush[8][64], vsh[8][16];

    const int tid = threadIdx.x, w = tid >> 5, l = tid & 31;
    const int b = blockIdx.x * 8 + w;

    for (int i = tid; i < D_ * E_;  i += 256) W0s[i] = W0[i];
    for (int i = tid; i < E_ * G4_; i += 256) Wbs[i] = Wb[i];
    for (int i = tid; i < 32 * 64;  i += 256) W1s[i] = W1[i];
    for (int i = tid; i < 64 * 16;  i += 256) W2s[i] = W2[i];
    if (tid < 32) W3s[tid] = W3[tid];
    if (tid < 64) { b0s[tid] = b0[tid]; bbs[tid] = bb[tid]; b1s[tid] = b1[tid]; }
    if (tid < 16) b2s[tid] = b2[tid];
    if (tid < 2)  b3s[tid] = b3[tid];
    __syncthreads();

    if (l < 20) xsh[w][l] = x[((size_t)b * T_ + (T_ - 1)) * D_ + l];
    __syncwarp();

    float a0 = b0s[l], a1 = b0s[l + 32];
    #pragma unroll
    for (int d = 0; d < D_; d++) {
        float xv = xsh[w][d];
        a0 = fmaf(xv, W0s[d * E_ + l],      a0);
        a1 = fmaf(xv, W0s[d * E_ + l + 32], a1);
    }
    a0 = fmaxf(a0, 0.f); a1 = fmaxf(a1, 0.f);
    hes[w][l]      = make_float2(a0, a0);
    hes[w][l + 32] = make_float2(a1, a1);
    __syncwarp();

    const int j = l & 15;
    const int cA = (l < 16) ? l : (32 + j);
    const int cB = cA + 16;
    u64 acc = pack2(bbs[cA], bbs[cB]);
    #pragma unroll 8
    for (int k = 0; k < E_; k++) {
        u64 hd = *(const u64*)&hes[w][k];
        acc = fma2(hd, pack2(Wbs[k * G4_ + cA], Wbs[k * G4_ + cB]), acc);
    }
    float xA, xB; unpack2(acc, xA, xB);

    float bU, kV, aV, bV;
    if (l < 16) { bU = 0.f;  kV = 1.f;  aV = 1.f;  bV = 0.f;  }
    else        { bU = 0.5f; kV = 0.5f; aV = 0.5f; bV = 0.5f; }
    float u = fmaf(0.5f, tanha(fmaf(0.5f, xA, bU)), 0.5f);
    float v = fmaf(aV, tanha(kV * xB), bV);
    float so = __shfl_down_sync(0xffffffffu, v, 16);
    if (l < 16) {
        float cc = u * v;
        hbs[w][l] = so * tanha(cc);
    }
    __syncwarp();

    insh[w][l] = (l < 16) ? g_hf[b * H_ + l] : hbs[w][l - 16];
    __syncwarp();

    float u0 = b1s[l], u1 = b1s[l + 32];
    #pragma unroll 8
    for (int k = 0; k < 32; k++) {
        float t = insh[w][k];
        u0 = fmaf(t, W1s[k * 64 + l],      u0);
        u1 = fmaf(t, W1s[k * 64 + l + 32], u1);
    }
    ush[w][l]      = fmaxf(u0, 0.f);
    ush[w][l + 32] = fmaxf(u1, 0.f);
    __syncwarp();

    if (l < 16) {
        float a = b2s[l];
        #pragma unroll 8
        for (int k = 0; k < 64; k++) a = fmaf(ush[w][k], W2s[k * 16 + l], a);
        vsh[w][l] = fmaxf(a, 0.f);
    }
    __syncwarp();

    if (l < 2) {
        float a = b3s[l];
        #pragma unroll
        for (int k = 0; k < 16; k++) a = fmaf(vsh[w][k], W3s[k * 2 + l], a);
        out[b * 2 + l] = a;
    }
}

extern "C" void kernel_launch(void* const* d_in, const int* in_sizes, int n_in,
                              void* d_out, int out_size)
{
    (void)in_sizes; (void)n_in; (void)out_size;
    const float* x  = (const float*)d_in[0];
    const float* W0 = (const float*)d_in[1];
    const float* b0 = (const float*)d_in[2];
    const float* Wf = (const float*)d_in[3];
    const float* bf = (const float*)d_in[4];
    const float* Wb = (const float*)d_in[5];
    const float* bb = (const float*)d_in[6];
    const float* W1 = (const float*)d_in[7];
    const float* b1 = (const float*)d_in[8];
    const float* W2 = (const float*)d_in[9];
    const float* b2 = (const float*)d_in[10];
    const float* W3 = (const float*)d_in[11];
    const float* b3 = (const float*)d_in[12];
    float* out = (float*)d_out;

    cudaFuncSetAttribute(k_phase1, cudaFuncAttributeMaxDynamicSharedMemorySize, (int)SMEM1);

    k_prep  <<<24, 256>>>(Wf, W0);
    k_phase1<<<B_,     256, SMEM1>>>(x, b0, bf);
    k_scan  <<<B_ / 4, 128>>>(Wf);
    k_tail  <<<B_ / 8, 256>>>(x, W0, b0, Wb, bb, W1, b1, W2, b2, W3, b3, out);
}